// round 13
// baseline (speedup 1.0000x reference)
#include <cuda_runtime.h>
#include <cuda_bf16.h>
#include <cuda_fp16.h>
#include <cstdint>

#define N_NODES 100000
#define N_EDGES 3200000
#define IN_CH   512
#define HIDDEN  64
#define LOC_OUT 16
#define OUT_CH  40

// ---------------- scratch (static device globals; no runtime alloc) ----------
__device__ __align__(16) int    d_degi[N_NODES];            // edge in-degree
__device__ __align__(16) float  d_dinv[N_NODES];            // 1/sqrt(deg+1)
__device__ __align__(16) __half d_g1  [N_NODES * HIDDEN];   // fp16: dinv*(X@W1)
__device__ __align__(16) float  d_g2  [N_NODES * LOC_OUT];  // dinv * (x1 @ W2)
__device__ __align__(16) float  d_x2  [N_NODES * LOC_OUT];  // layer-2 output (z0)
__device__ __align__(16) int    d_off [N_NODES + 1];        // CSR offsets (by dst)
__device__ __align__(16) int    d_cur [N_NODES];            // placement cursors
__device__ __align__(16) int    d_src [N_EDGES];            // dst-sorted source ids
__device__ int d_idx_nonzero_odd;   // >0  =>  edge_index is int32

// ---------------- edge index fetch: handles int64 or int32 buffers -----------
__device__ __forceinline__ int load_edge(const void* ei, unsigned int pos) {
    if (d_idx_nonzero_odd == 0) {          // int64 payload (high words all 0)
        return (int)((const long long*)ei)[pos];
    } else {                               // int32 payload
        return ((const int*)ei)[pos];
    }
}

// ---------------- fp16 quad -> float4 ----------------------------------------
__device__ __forceinline__ float4 h4_to_f4(uint2 r) {
    __half2 a = *reinterpret_cast<__half2*>(&r.x);
    __half2 b = *reinterpret_cast<__half2*>(&r.y);
    float2 fa = __half22float2(a), fb = __half22float2(b);
    return make_float4(fa.x, fa.y, fb.x, fb.y);
}

// ---------------- dtype detection: sample odd int32 slots --------------------
__global__ void k_detect(const int* __restrict__ ei32) {
    int t = threadIdx.x;
    int nz = 0;
    #pragma unroll
    for (int j = 0; j < 8; j++) nz |= ei32[2 * (t * 8 + j) + 1];
    if (nz) atomicOr(&d_idx_nonzero_odd, 1);
}

// ---------------- init: zero degree histogram + flag -------------------------
__global__ void k_init() {
    int i = blockIdx.x * blockDim.x + threadIdx.x;
    if (i < N_NODES) d_degi[i] = 0;
    if (i == 0)      d_idx_nonzero_odd = 0;
}

// ---------------- degree count over targets (col = edge_index[1]) ------------
__global__ void k_count(const void* __restrict__ ei) {
    unsigned int e = blockIdx.x * blockDim.x + threadIdx.x;
    if (e < N_EDGES) {
        int c = load_edge(ei, N_EDGES + e);
        if ((unsigned)c < N_NODES) atomicAdd(&d_degi[c], 1);
    }
}

// ================= mma.sync GEMM1:  g1 = dinv * (X @ W1)  (fp16 out) =========
#define SWZ(o) ((o) ^ (((o) >> 3) & 0x70))
#define KC 64

__device__ __forceinline__ uint32_t smem_u32(const void* p) {
    uint32_t a;
    asm("{ .reg .u64 t; cvta.to.shared.u64 t, %1; cvt.u32.u64 %0, t; }"
        : "=r"(a) : "l"(p));
    return a;
}
__device__ __forceinline__ void ldsm_x4(uint32_t* r, uint32_t addr) {
    asm volatile("ldmatrix.sync.aligned.m8n8.x4.shared.b16 {%0,%1,%2,%3}, [%4];"
                 : "=r"(r[0]), "=r"(r[1]), "=r"(r[2]), "=r"(r[3]) : "r"(addr));
}
__device__ __forceinline__ void ldsm_x4_t(uint32_t* r, uint32_t addr) {
    asm volatile("ldmatrix.sync.aligned.m8n8.x4.trans.shared.b16 {%0,%1,%2,%3}, [%4];"
                 : "=r"(r[0]), "=r"(r[1]), "=r"(r[2]), "=r"(r[3]) : "r"(addr));
}
__device__ __forceinline__ void mma16816(float* c, const uint32_t* a,
                                         uint32_t b0, uint32_t b1) {
    asm volatile(
        "mma.sync.aligned.m16n8k16.row.col.f32.bf16.bf16.f32 "
        "{%0,%1,%2,%3}, {%4,%5,%6,%7}, {%8,%9}, {%0,%1,%2,%3};"
        : "+f"(c[0]), "+f"(c[1]), "+f"(c[2]), "+f"(c[3])
        : "r"(a[0]), "r"(a[1]), "r"(a[2]), "r"(a[3]), "r"(b0), "r"(b1));
}
__device__ __forceinline__ uint32_t pack_bf16x2(float a, float b) {
    uint32_t r;
    asm("cvt.rn.bf16x2.f32 %0, %1, %2;" : "=r"(r) : "f"(b), "f"(a));
    return r;
}

__global__ __launch_bounds__(256, 2) void k_gemm1(const float* __restrict__ X,
                                                  const float* __restrict__ W1) {
    __shared__ __align__(16) char sAh[128 * 128];   // 16 KB
    __shared__ __align__(16) char sAl[128 * 128];   // 16 KB
    __shared__ __align__(16) char sBh[KC * 128];    // 8 KB
    __shared__ __align__(16) char sBl[KC * 128];    // 8 KB
    int tid = threadIdx.x;
    int wid = tid >> 5, lane = tid & 31;
    int row0 = blockIdx.x * 128;
    int wr0 = wid * 16;

    float acc[8][4];
    #pragma unroll
    for (int i = 0; i < 8; i++)
        #pragma unroll
        for (int j = 0; j < 4; j++) acc[i][j] = 0.f;

    uint32_t aAh = smem_u32(sAh), aAl = smem_u32(sAl);
    uint32_t aBh = smem_u32(sBh), aBl = smem_u32(sBl);

    uint32_t a_row = (uint32_t)(wr0 + (lane & 15));
    uint32_t a_kh  = (uint32_t)((lane >> 4) * 16);
    uint32_t b_krow = (uint32_t)((lane & 7) + ((lane >> 3) & 1) * 8);
    uint32_t b_nh   = (uint32_t)((lane >> 4) * 16);

    for (int c = 0; c < IN_CH / KC; c++) {
        int k0 = c * KC;
        #pragma unroll
        for (int it = 0; it < 8; it++) {
            int idx = it * 256 + tid;
            int row = idx >> 4;
            int kq = (idx & 15) * 4;
            int gr = row0 + row;
            float4 v = (gr < N_NODES)
                     ? *(const float4*)&X[(size_t)gr * IN_CH + k0 + kq]
                     : make_float4(0.f, 0.f, 0.f, 0.f);
            uint32_t h0 = pack_bf16x2(v.x, v.y);
            uint32_t h1 = pack_bf16x2(v.z, v.w);
            float lx = v.x - __bfloat162float(__ushort_as_bfloat16((unsigned short)(h0 & 0xFFFF)));
            float ly = v.y - __bfloat162float(__ushort_as_bfloat16((unsigned short)(h0 >> 16)));
            float lz = v.z - __bfloat162float(__ushort_as_bfloat16((unsigned short)(h1 & 0xFFFF)));
            float lw = v.w - __bfloat162float(__ushort_as_bfloat16((unsigned short)(h1 >> 16)));
            uint32_t l0 = pack_bf16x2(lx, ly);
            uint32_t l1 = pack_bf16x2(lz, lw);
            uint32_t o = SWZ((uint32_t)(row * 128 + kq * 2));
            *(uint2*)(sAh + o) = make_uint2(h0, h1);
            *(uint2*)(sAl + o) = make_uint2(l0, l1);
        }
        #pragma unroll
        for (int it = 0; it < 4; it++) {
            int idx = it * 256 + tid;
            int kk = idx >> 4;
            int n0 = (idx & 15) * 4;
            float4 v = *(const float4*)&W1[(size_t)(k0 + kk) * HIDDEN + n0];
            uint32_t h0 = pack_bf16x2(v.x, v.y);
            uint32_t h1 = pack_bf16x2(v.z, v.w);
            float lx = v.x - __bfloat162float(__ushort_as_bfloat16((unsigned short)(h0 & 0xFFFF)));
            float ly = v.y - __bfloat162float(__ushort_as_bfloat16((unsigned short)(h0 >> 16)));
            float lz = v.z - __bfloat162float(__ushort_as_bfloat16((unsigned short)(h1 & 0xFFFF)));
            float lw = v.w - __bfloat162float(__ushort_as_bfloat16((unsigned short)(h1 >> 16)));
            uint32_t l0 = pack_bf16x2(lx, ly);
            uint32_t l1 = pack_bf16x2(lz, lw);
            uint32_t o = SWZ((uint32_t)(kk * 128 + n0 * 2));
            *(uint2*)(sBh + o) = make_uint2(h0, h1);
            *(uint2*)(sBl + o) = make_uint2(l0, l1);
        }
        __syncthreads();

        #pragma unroll
        for (int k16 = 0; k16 < KC / 16; k16++) {
            uint32_t ao = SWZ(a_row * 128 + (uint32_t)k16 * 32 + a_kh);
            uint32_t ah[4], al[4];
            ldsm_x4(ah, aAh + ao);
            ldsm_x4(al, aAl + ao);
            #pragma unroll
            for (int p = 0; p < 4; p++) {
                uint32_t bo = SWZ(((uint32_t)k16 * 16 + b_krow) * 128
                                  + (uint32_t)p * 32 + b_nh);
                uint32_t bh[4], bl[4];
                ldsm_x4_t(bh, aBh + bo);
                ldsm_x4_t(bl, aBl + bo);
                mma16816(acc[2 * p],     ah, bh[0], bh[1]);
                mma16816(acc[2 * p],     ah, bl[0], bl[1]);
                mma16816(acc[2 * p],     al, bh[0], bh[1]);
                mma16816(acc[2 * p + 1], ah, bh[2], bh[3]);
                mma16816(acc[2 * p + 1], ah, bl[2], bl[3]);
                mma16816(acc[2 * p + 1], al, bh[2], bh[3]);
            }
        }
        __syncthreads();
    }

    // ---- epilogue: scale by dinv, convert to fp16, store; persist dinv ------
    int gid = lane >> 2, tig = lane & 3;
    int r0 = row0 + wr0 + gid;
    int r1 = r0 + 8;
    float di0 = 0.f, di1 = 0.f;
    if (r0 < N_NODES) di0 = rsqrtf((float)(d_degi[r0] + 1));
    if (r1 < N_NODES) di1 = rsqrtf((float)(d_degi[r1] + 1));
    if (tig == 0) {
        if (r0 < N_NODES) d_dinv[r0] = di0;
        if (r1 < N_NODES) d_dinv[r1] = di1;
    }
    #pragma unroll
    for (int nt = 0; nt < 8; nt++) {
        int col = nt * 8 + tig * 2;
        if (r0 < N_NODES)
            *(__half2*)&d_g1[(size_t)r0 * HIDDEN + col] =
                __floats2half2_rn(di0 * acc[nt][0], di0 * acc[nt][1]);
        if (r1 < N_NODES)
            *(__half2*)&d_g1[(size_t)r1 * HIDDEN + col] =
                __floats2half2_rn(di1 * acc[nt][2], di1 * acc[nt][3]);
    }
}

// ---------------- exclusive scan of degrees -> CSR offsets (1 block) ---------
__global__ __launch_bounds__(1024) void k_scan() {
    __shared__ int s[1024];
    const int C = (N_NODES + 1023) / 1024;       // 98
    int t = threadIdx.x;
    int beg = t * C;
    int end = beg + C; if (end > N_NODES) end = N_NODES;
    int loc = 0;
    for (int i = beg; i < end; i++) loc += d_degi[i];
    s[t] = loc;
    __syncthreads();
    for (int o = 1; o < 1024; o <<= 1) {
        int v = (t >= o) ? s[t - o] : 0;
        __syncthreads();
        s[t] += v;
        __syncthreads();
    }
    int run = (t > 0) ? s[t - 1] : 0;
    for (int i = beg; i < end; i++) {
        d_off[i] = run;
        d_cur[i] = run;
        run += d_degi[i];
    }
    if (t == 1023) d_off[N_NODES] = s[1023];
}

// ---------------- place edges into dst-sorted source list --------------------
__global__ void k_place(const void* __restrict__ ei) {
    unsigned int e = blockIdx.x * blockDim.x + threadIdx.x;
    if (e >= N_EDGES) return;
    int r = load_edge(ei, e);
    int c = load_edge(ei, N_EDGES + e);
    if ((unsigned)r >= N_NODES || (unsigned)c >= N_NODES) return;
    int pos = atomicAdd(&d_cur[c], 1);
    d_src[pos] = r;
}

// ---------------- fused layer-1 aggregate + relu + GEMM2 ---------------------
// 16 nodes per block, 16 threads per node; g1 gathered as fp16 (8B per lane).
#define X1_STRIDE 68
#define W2T_STRIDE 65
__global__ __launch_bounds__(256) void k_aggmid(const float* __restrict__ b1,
                                                const float* __restrict__ W2) {
    __shared__ float x1s[16 * X1_STRIDE];        // 16 rows of 64 (+pad)
    __shared__ float w2t[LOC_OUT * W2T_STRIDE];  // W2T[j][k] = W2[k*16+j]
    int tid = threadIdx.x;
    for (int i = tid; i < HIDDEN * LOC_OUT; i += 256) {
        int k = i >> 4, j = i & 15;
        w2t[j * W2T_STRIDE + k] = W2[i];
    }

    int lane = tid & 15;
    int local = tid >> 4;                        // 0..15
    int n = blockIdx.x * 16 + local;
    bool alive = (n < N_NODES);
    float di = 0.f;

    if (alive) {
        const __half* g1 = d_g1;
        size_t ch = (size_t)lane * 4;
        // self loop term
        float4 s0 = h4_to_f4(*(const uint2*)&g1[(size_t)n * HIDDEN + ch]);
        float4 s1 = make_float4(0.f, 0.f, 0.f, 0.f);
        float4 s2 = make_float4(0.f, 0.f, 0.f, 0.f);
        float4 s3 = make_float4(0.f, 0.f, 0.f, 0.f);
        int beg = d_off[n], end = d_off[n + 1];
        int i = beg;
        for (; i + 3 < end; i += 4) {
            int a0 = d_src[i],     a1 = d_src[i + 1];
            int a2 = d_src[i + 2], a3 = d_src[i + 3];
            uint2 r0 = *(const uint2*)&g1[(size_t)a0 * HIDDEN + ch];
            uint2 r1 = *(const uint2*)&g1[(size_t)a1 * HIDDEN + ch];
            uint2 r2 = *(const uint2*)&g1[(size_t)a2 * HIDDEN + ch];
            uint2 r3 = *(const uint2*)&g1[(size_t)a3 * HIDDEN + ch];
            float4 v0 = h4_to_f4(r0), v1 = h4_to_f4(r1);
            float4 v2 = h4_to_f4(r2), v3 = h4_to_f4(r3);
            s0.x += v0.x; s0.y += v0.y; s0.z += v0.z; s0.w += v0.w;
            s1.x += v1.x; s1.y += v1.y; s1.z += v1.z; s1.w += v1.w;
            s2.x += v2.x; s2.y += v2.y; s2.z += v2.z; s2.w += v2.w;
            s3.x += v3.x; s3.y += v3.y; s3.z += v3.z; s3.w += v3.w;
        }
        for (; i < end; i++) {
            float4 v = h4_to_f4(*(const uint2*)&g1[(size_t)d_src[i] * HIDDEN + ch]);
            s0.x += v.x; s0.y += v.y; s0.z += v.z; s0.w += v.w;
        }
        s0.x += s1.x + s2.x + s3.x;
        s0.y += s1.y + s2.y + s3.y;
        s0.z += s1.z + s2.z + s3.z;
        s0.w += s1.w + s2.w + s3.w;
        di = d_dinv[n];
        float4 bb = *(const float4*)&b1[lane * 4];
        float* xr = &x1s[local * X1_STRIDE + lane * 4];
        xr[0] = fmaxf(di * s0.x + bb.x, 0.f);
        xr[1] = fmaxf(di * s0.y + bb.y, 0.f);
        xr[2] = fmaxf(di * s0.z + bb.z, 0.f);
        xr[3] = fmaxf(di * s0.w + bb.w, 0.f);
    }
    __syncthreads();

    if (!alive) return;
    const float* xr = &x1s[local * X1_STRIDE];
    const float* wr = &w2t[lane * W2T_STRIDE];
    float acc = 0.f;
    #pragma unroll
    for (int k = 0; k < HIDDEN; k += 4) {
        float4 x = *(const float4*)&xr[k];       // broadcast across 16 lanes
        acc += x.x * wr[k + 0];
        acc += x.y * wr[k + 1];
        acc += x.z * wr[k + 2];
        acc += x.w * wr[k + 3];
    }
    d_g2[n * LOC_OUT + lane] = di * acc;         // fully coalesced
}

// ---------------- layer-2 aggregate:  x2 = dinv*(sum+self) + b2 --------------
__global__ __launch_bounds__(256) void k_agg2(const float* __restrict__ b2) {
    int tid = threadIdx.x;
    int lane = tid & 3;
    int n = blockIdx.x * 64 + (tid >> 2);
    if (n >= N_NODES) return;

    const float4* g2 = (const float4*)d_g2;
    float4 s0 = g2[n * 4 + lane];                // self loop term
    float4 s1 = make_float4(0.f, 0.f, 0.f, 0.f);
    float4 s2 = make_float4(0.f, 0.f, 0.f, 0.f);
    float4 s3 = make_float4(0.f, 0.f, 0.f, 0.f);
    int beg = d_off[n], end = d_off[n + 1];
    int i = beg;
    for (; i + 3 < end; i += 4) {
        int a0 = d_src[i],     a1 = d_src[i + 1];
        int a2 = d_src[i + 2], a3 = d_src[i + 3];
        float4 v0 = g2[a0 * 4 + lane];
        float4 v1 = g2[a1 * 4 + lane];
        float4 v2 = g2[a2 * 4 + lane];
        float4 v3 = g2[a3 * 4 + lane];
        s0.x += v0.x; s0.y += v0.y; s0.z += v0.z; s0.w += v0.w;
        s1.x += v1.x; s1.y += v1.y; s1.z += v1.z; s1.w += v1.w;
        s2.x += v2.x; s2.y += v2.y; s2.z += v2.z; s2.w += v2.w;
        s3.x += v3.x; s3.y += v3.y; s3.z += v3.z; s3.w += v3.w;
    }
    for (; i < end; i++) {
        float4 v = g2[d_src[i] * 4 + lane];
        s0.x += v.x; s0.y += v.y; s0.z += v.z; s0.w += v.w;
    }
    s0.x += s1.x + s2.x + s3.x;
    s0.y += s1.y + s2.y + s3.y;
    s0.z += s1.z + s2.z + s3.z;
    s0.w += s1.w + s2.w + s3.w;
    float di = d_dinv[n];
    float4 bb = *(const float4*)&b2[lane * 4];
    float4 r;
    r.x = di * s0.x + bb.x;
    r.y = di * s0.y + bb.y;
    r.z = di * s0.z + bb.z;
    r.w = di * s0.w + bb.w;
    ((float4*)d_x2)[n * 4 + lane] = r;
}

// ---------------- final: attention pool over {x2, glob} + linear head --------
__global__ __launch_bounds__(256) void k_final(const float* __restrict__ glob,
                                               const float* __restrict__ aw1,
                                               const float* __restrict__ ab1,
                                               const float* __restrict__ aw2,
                                               const float* __restrict__ lw,
                                               const float* __restrict__ lb,
                                               float* __restrict__ out) {
    __shared__ float s_aw1[256], s_ab1[16], s_aw2[16];
    __shared__ float s_lw[LOC_OUT * OUT_CH], s_lb[OUT_CH];
    int tid = threadIdx.x;
    if (tid < 256) s_aw1[tid] = aw1[tid];
    if (tid < 16) { s_ab1[tid] = ab1[tid]; s_aw2[tid] = aw2[tid]; }
    for (int i = tid; i < LOC_OUT * OUT_CH; i += 256) s_lw[i] = lw[i];
    if (tid < OUT_CH) s_lb[tid] = lb[tid];
    __syncthreads();

    int n = blockIdx.x * 256 + tid;
    if (n >= N_NODES) return;
    float z0[16], z1[16];
    const float4* x2 = (const float4*)&d_x2[n * LOC_OUT];
    const float4* gl = (const float4*)&glob[n * LOC_OUT];
    #pragma unroll
    for (int q = 0; q < 4; q++) {
        float4 a = x2[q], e = gl[q];
        z0[q*4+0] = a.x; z0[q*4+1] = a.y; z0[q*4+2] = a.z; z0[q*4+3] = a.w;
        z1[q*4+0] = e.x; z1[q*4+1] = e.y; z1[q*4+2] = e.z; z1[q*4+3] = e.w;
    }
    float w0 = 0.f, w1 = 0.f;
    #pragma unroll
    for (int j = 0; j < 16; j++) {
        float s0 = s_ab1[j], s1 = s_ab1[j];
        #pragma unroll
        for (int i2 = 0; i2 < 16; i2++) {
            s0 += z0[i2] * s_aw1[i2 * 16 + j];
            s1 += z1[i2] * s_aw1[i2 * 16 + j];
        }
        w0 += tanhf(s0) * s_aw2[j];
        w1 += tanhf(s1) * s_aw2[j];
    }
    float beta0 = 1.f / (1.f + expf(w1 - w0));   // softmax over 2 slots
    float beta1 = 1.f - beta0;
    float emb[16];
    #pragma unroll
    for (int i2 = 0; i2 < 16; i2++) emb[i2] = beta0 * z0[i2] + beta1 * z1[i2];
    #pragma unroll
    for (int j = 0; j < OUT_CH; j++) {
        float o = s_lb[j];
        #pragma unroll
        for (int i2 = 0; i2 < 16; i2++) o += emb[i2] * s_lw[i2 * OUT_CH + j];
        out[(size_t)n * OUT_CH + j] = o;
    }
}

// ---------------- launch ------------------------------------------------------
extern "C" void kernel_launch(void* const* d_in, const int* in_sizes, int n_in,
                              void* d_out, int out_size) {
    const float* X    = (const float*)d_in[0];
    const void*  ei   = d_in[1];
    const float* glob = (const float*)d_in[2];
    const float* W1   = (const float*)d_in[3];
    const float* b1   = (const float*)d_in[4];
    const float* W2   = (const float*)d_in[5];
    const float* b2   = (const float*)d_in[6];
    const float* aw1  = (const float*)d_in[7];
    const float* ab1  = (const float*)d_in[8];
    const float* aw2  = (const float*)d_in[9];
    const float* lw   = (const float*)d_in[10];
    const float* lb   = (const float*)d_in[11];
    float* out = (float*)d_out;

    k_init  <<<(N_NODES + 255) / 256, 256>>>();                 // 0
    k_detect<<<1, 256>>>((const int*)ei);                       // 1
    k_count <<<(N_EDGES + 255) / 256, 256>>>(ei);               // 2
    k_gemm1 <<<(N_NODES + 127) / 128, 256>>>(X, W1);            // 3  <- profiled
    k_scan  <<<1, 1024>>>();                                    // 4
    k_place <<<(N_EDGES + 255) / 256, 256>>>(ei);               // 5
    k_aggmid<<<(N_NODES + 15) / 16, 256>>>(b1, W2);             // 6
    k_agg2  <<<(N_NODES + 63) / 64, 256>>>(b2);                 // 7
    k_final <<<(N_NODES + 255) / 256, 256>>>(glob, aw1, ab1, aw2, lw, lb, out);  // 8
}

// round 14
// speedup vs baseline: 1.4773x; 1.4773x over previous
#include <cuda_runtime.h>
#include <cuda_bf16.h>
#include <cuda_fp16.h>
#include <cstdint>

#define N_NODES 100000
#define N_EDGES 3200000
#define IN_CH   512
#define HIDDEN  64
#define LOC_OUT 16
#define OUT_CH  40

// ---------------- scratch (static device globals; no runtime alloc) ----------
__device__ __align__(16) int    d_degi[N_NODES];            // edge in-degree
__device__ __align__(16) float  d_dinv[N_NODES];            // 1/sqrt(deg+1)
__device__ __align__(16) __half d_g1  [N_NODES * HIDDEN];   // fp16: dinv*(X@W1)
__device__ __align__(16) float  d_g2  [N_NODES * LOC_OUT];  // dinv * (x1 @ W2)
__device__ __align__(16) float  d_x2  [N_NODES * LOC_OUT];  // layer-2 output (z0)
__device__ __align__(16) int    d_off [N_NODES + 1];        // CSR offsets (by dst)
__device__ __align__(16) int    d_cur [N_NODES];            // placement cursors
__device__ __align__(16) int    d_src [N_EDGES];            // dst-sorted source ids
__device__ int d_idx_nonzero_odd;   // >0  =>  edge_index is int32

// ---------------- edge index fetch: handles int64 or int32 buffers -----------
__device__ __forceinline__ int load_edge(const void* ei, unsigned int pos) {
    if (d_idx_nonzero_odd == 0) {          // int64 payload (high words all 0)
        return (int)((const long long*)ei)[pos];
    } else {                               // int32 payload
        return ((const int*)ei)[pos];
    }
}

// ---------------- fp16 quad -> float4 ----------------------------------------
__device__ __forceinline__ float4 h4_to_f4(uint2 r) {
    __half2 a = *reinterpret_cast<__half2*>(&r.x);
    __half2 b = *reinterpret_cast<__half2*>(&r.y);
    float2 fa = __half22float2(a), fb = __half22float2(b);
    return make_float4(fa.x, fa.y, fb.x, fb.y);
}

// ---------------- dtype detection: sample odd int32 slots --------------------
__global__ void k_detect(const int* __restrict__ ei32) {
    int t = threadIdx.x;
    int nz = 0;
    #pragma unroll
    for (int j = 0; j < 8; j++) nz |= ei32[2 * (t * 8 + j) + 1];
    if (nz) atomicOr(&d_idx_nonzero_odd, 1);
}

// ---------------- init: zero degree histogram + flag -------------------------
__global__ void k_init() {
    int i = blockIdx.x * blockDim.x + threadIdx.x;
    if (i < N_NODES) d_degi[i] = 0;
    if (i == 0)      d_idx_nonzero_odd = 0;
}

// ---------------- degree count over targets (col = edge_index[1]) ------------
__global__ void k_count(const void* __restrict__ ei) {
    unsigned int e = blockIdx.x * blockDim.x + threadIdx.x;
    if (e < N_EDGES) {
        int c = load_edge(ei, N_EDGES + e);
        if ((unsigned)c < N_NODES) atomicAdd(&d_degi[c], 1);
    }
}

// ================= mma.sync GEMM1:  g1 = dinv * (X @ W1)  (fp16 out) =========
#define SWZ(o) ((o) ^ (((o) >> 3) & 0x70))
#define KC 64

__device__ __forceinline__ uint32_t smem_u32(const void* p) {
    uint32_t a;
    asm("{ .reg .u64 t; cvta.to.shared.u64 t, %1; cvt.u32.u64 %0, t; }"
        : "=r"(a) : "l"(p));
    return a;
}
__device__ __forceinline__ void ldsm_x4(uint32_t* r, uint32_t addr) {
    asm volatile("ldmatrix.sync.aligned.m8n8.x4.shared.b16 {%0,%1,%2,%3}, [%4];"
                 : "=r"(r[0]), "=r"(r[1]), "=r"(r[2]), "=r"(r[3]) : "r"(addr));
}
__device__ __forceinline__ void ldsm_x4_t(uint32_t* r, uint32_t addr) {
    asm volatile("ldmatrix.sync.aligned.m8n8.x4.trans.shared.b16 {%0,%1,%2,%3}, [%4];"
                 : "=r"(r[0]), "=r"(r[1]), "=r"(r[2]), "=r"(r[3]) : "r"(addr));
}
__device__ __forceinline__ void mma16816(float* c, const uint32_t* a,
                                         uint32_t b0, uint32_t b1) {
    asm volatile(
        "mma.sync.aligned.m16n8k16.row.col.f32.bf16.bf16.f32 "
        "{%0,%1,%2,%3}, {%4,%5,%6,%7}, {%8,%9}, {%0,%1,%2,%3};"
        : "+f"(c[0]), "+f"(c[1]), "+f"(c[2]), "+f"(c[3])
        : "r"(a[0]), "r"(a[1]), "r"(a[2]), "r"(a[3]), "r"(b0), "r"(b1));
}
__device__ __forceinline__ uint32_t pack_bf16x2(float a, float b) {
    uint32_t r;
    asm("cvt.rn.bf16x2.f32 %0, %1, %2;" : "=r"(r) : "f"(b), "f"(a));
    return r;
}

__global__ __launch_bounds__(256, 2) void k_gemm1(const float* __restrict__ X,
                                                  const float* __restrict__ W1) {
    __shared__ __align__(16) char sAh[128 * 128];   // 16 KB
    __shared__ __align__(16) char sAl[128 * 128];   // 16 KB
    __shared__ __align__(16) char sBh[KC * 128];    // 8 KB
    __shared__ __align__(16) char sBl[KC * 128];    // 8 KB
    int tid = threadIdx.x;
    int wid = tid >> 5, lane = tid & 31;
    int row0 = blockIdx.x * 128;
    int wr0 = wid * 16;

    float acc[8][4];
    #pragma unroll
    for (int i = 0; i < 8; i++)
        #pragma unroll
        for (int j = 0; j < 4; j++) acc[i][j] = 0.f;

    uint32_t aAh = smem_u32(sAh), aAl = smem_u32(sAl);
    uint32_t aBh = smem_u32(sBh), aBl = smem_u32(sBl);

    uint32_t a_row = (uint32_t)(wr0 + (lane & 15));
    uint32_t a_kh  = (uint32_t)((lane >> 4) * 16);
    uint32_t b_krow = (uint32_t)((lane & 7) + ((lane >> 3) & 1) * 8);
    uint32_t b_nh   = (uint32_t)((lane >> 4) * 16);

    for (int c = 0; c < IN_CH / KC; c++) {
        int k0 = c * KC;
        #pragma unroll
        for (int it = 0; it < 8; it++) {
            int idx = it * 256 + tid;
            int row = idx >> 4;
            int kq = (idx & 15) * 4;
            int gr = row0 + row;
            float4 v = (gr < N_NODES)
                     ? *(const float4*)&X[(size_t)gr * IN_CH + k0 + kq]
                     : make_float4(0.f, 0.f, 0.f, 0.f);
            uint32_t h0 = pack_bf16x2(v.x, v.y);
            uint32_t h1 = pack_bf16x2(v.z, v.w);
            float lx = v.x - __bfloat162float(__ushort_as_bfloat16((unsigned short)(h0 & 0xFFFF)));
            float ly = v.y - __bfloat162float(__ushort_as_bfloat16((unsigned short)(h0 >> 16)));
            float lz = v.z - __bfloat162float(__ushort_as_bfloat16((unsigned short)(h1 & 0xFFFF)));
            float lw = v.w - __bfloat162float(__ushort_as_bfloat16((unsigned short)(h1 >> 16)));
            uint32_t l0 = pack_bf16x2(lx, ly);
            uint32_t l1 = pack_bf16x2(lz, lw);
            uint32_t o = SWZ((uint32_t)(row * 128 + kq * 2));
            *(uint2*)(sAh + o) = make_uint2(h0, h1);
            *(uint2*)(sAl + o) = make_uint2(l0, l1);
        }
        #pragma unroll
        for (int it = 0; it < 4; it++) {
            int idx = it * 256 + tid;
            int kk = idx >> 4;
            int n0 = (idx & 15) * 4;
            float4 v = *(const float4*)&W1[(size_t)(k0 + kk) * HIDDEN + n0];
            uint32_t h0 = pack_bf16x2(v.x, v.y);
            uint32_t h1 = pack_bf16x2(v.z, v.w);
            float lx = v.x - __bfloat162float(__ushort_as_bfloat16((unsigned short)(h0 & 0xFFFF)));
            float ly = v.y - __bfloat162float(__ushort_as_bfloat16((unsigned short)(h0 >> 16)));
            float lz = v.z - __bfloat162float(__ushort_as_bfloat16((unsigned short)(h1 & 0xFFFF)));
            float lw = v.w - __bfloat162float(__ushort_as_bfloat16((unsigned short)(h1 >> 16)));
            uint32_t l0 = pack_bf16x2(lx, ly);
            uint32_t l1 = pack_bf16x2(lz, lw);
            uint32_t o = SWZ((uint32_t)(kk * 128 + n0 * 2));
            *(uint2*)(sBh + o) = make_uint2(h0, h1);
            *(uint2*)(sBl + o) = make_uint2(l0, l1);
        }
        __syncthreads();

        #pragma unroll
        for (int k16 = 0; k16 < KC / 16; k16++) {
            uint32_t ao = SWZ(a_row * 128 + (uint32_t)k16 * 32 + a_kh);
            uint32_t ah[4], al[4];
            ldsm_x4(ah, aAh + ao);
            ldsm_x4(al, aAl + ao);
            #pragma unroll
            for (int p = 0; p < 4; p++) {
                uint32_t bo = SWZ(((uint32_t)k16 * 16 + b_krow) * 128
                                  + (uint32_t)p * 32 + b_nh);
                uint32_t bh[4], bl[4];
                ldsm_x4_t(bh, aBh + bo);
                ldsm_x4_t(bl, aBl + bo);
                mma16816(acc[2 * p],     ah, bh[0], bh[1]);
                mma16816(acc[2 * p],     ah, bl[0], bl[1]);
                mma16816(acc[2 * p],     al, bh[0], bh[1]);
                mma16816(acc[2 * p + 1], ah, bh[2], bh[3]);
                mma16816(acc[2 * p + 1], ah, bl[2], bl[3]);
                mma16816(acc[2 * p + 1], al, bh[2], bh[3]);
            }
        }
        __syncthreads();
    }

    // ---- epilogue: scale by dinv, convert to fp16, store; persist dinv ------
    int gid = lane >> 2, tig = lane & 3;
    int r0 = row0 + wr0 + gid;
    int r1 = r0 + 8;
    float di0 = 0.f, di1 = 0.f;
    if (r0 < N_NODES) di0 = rsqrtf((float)(d_degi[r0] + 1));
    if (r1 < N_NODES) di1 = rsqrtf((float)(d_degi[r1] + 1));
    if (tig == 0) {
        if (r0 < N_NODES) d_dinv[r0] = di0;
        if (r1 < N_NODES) d_dinv[r1] = di1;
    }
    #pragma unroll
    for (int nt = 0; nt < 8; nt++) {
        int col = nt * 8 + tig * 2;
        if (r0 < N_NODES)
            *(__half2*)&d_g1[(size_t)r0 * HIDDEN + col] =
                __floats2half2_rn(di0 * acc[nt][0], di0 * acc[nt][1]);
        if (r1 < N_NODES)
            *(__half2*)&d_g1[(size_t)r1 * HIDDEN + col] =
                __floats2half2_rn(di1 * acc[nt][2], di1 * acc[nt][3]);
    }
}

// ---------------- exclusive scan of degrees -> CSR offsets (1 block) ---------
__global__ __launch_bounds__(1024) void k_scan() {
    __shared__ int s[1024];
    const int C = (N_NODES + 1023) / 1024;       // 98
    int t = threadIdx.x;
    int beg = t * C;
    int end = beg + C; if (end > N_NODES) end = N_NODES;
    int loc = 0;
    for (int i = beg; i < end; i++) loc += d_degi[i];
    s[t] = loc;
    __syncthreads();
    for (int o = 1; o < 1024; o <<= 1) {
        int v = (t >= o) ? s[t - o] : 0;
        __syncthreads();
        s[t] += v;
        __syncthreads();
    }
    int run = (t > 0) ? s[t - 1] : 0;
    for (int i = beg; i < end; i++) {
        d_off[i] = run;
        d_cur[i] = run;
        run += d_degi[i];
    }
    if (t == 1023) d_off[N_NODES] = s[1023];
}

// ---------------- place edges into dst-sorted source list --------------------
__global__ void k_place(const void* __restrict__ ei) {
    unsigned int e = blockIdx.x * blockDim.x + threadIdx.x;
    if (e >= N_EDGES) return;
    int r = load_edge(ei, e);
    int c = load_edge(ei, N_EDGES + e);
    if ((unsigned)r >= N_NODES || (unsigned)c >= N_NODES) return;
    int pos = atomicAdd(&d_cur[c], 1);
    d_src[pos] = r;
}

// ---------------- fused layer-1 aggregate + relu + GEMM2 ---------------------
// 16 nodes per block, 16 threads per node; g1 gathered as fp16 (8B per lane).
#define X1_STRIDE 68
#define W2T_STRIDE 65
__global__ __launch_bounds__(256) void k_aggmid(const float* __restrict__ b1,
                                                const float* __restrict__ W2) {
    __shared__ float x1s[16 * X1_STRIDE];        // 16 rows of 64 (+pad)
    __shared__ float w2t[LOC_OUT * W2T_STRIDE];  // W2T[j][k] = W2[k*16+j]
    int tid = threadIdx.x;
    for (int i = tid; i < HIDDEN * LOC_OUT; i += 256) {
        int k = i >> 4, j = i & 15;
        w2t[j * W2T_STRIDE + k] = W2[i];
    }

    int lane = tid & 15;
    int local = tid >> 4;                        // 0..15
    int n = blockIdx.x * 16 + local;
    bool alive = (n < N_NODES);
    float di = 0.f;

    if (alive) {
        const __half* g1 = d_g1;
        size_t ch = (size_t)lane * 4;
        // self loop term
        float4 s0 = h4_to_f4(*(const uint2*)&g1[(size_t)n * HIDDEN + ch]);
        float4 s1 = make_float4(0.f, 0.f, 0.f, 0.f);
        float4 s2 = make_float4(0.f, 0.f, 0.f, 0.f);
        float4 s3 = make_float4(0.f, 0.f, 0.f, 0.f);
        int beg = d_off[n], end = d_off[n + 1];
        int i = beg;
        for (; i + 3 < end; i += 4) {
            int a0 = d_src[i],     a1 = d_src[i + 1];
            int a2 = d_src[i + 2], a3 = d_src[i + 3];
            uint2 r0 = *(const uint2*)&g1[(size_t)a0 * HIDDEN + ch];
            uint2 r1 = *(const uint2*)&g1[(size_t)a1 * HIDDEN + ch];
            uint2 r2 = *(const uint2*)&g1[(size_t)a2 * HIDDEN + ch];
            uint2 r3 = *(const uint2*)&g1[(size_t)a3 * HIDDEN + ch];
            float4 v0 = h4_to_f4(r0), v1 = h4_to_f4(r1);
            float4 v2 = h4_to_f4(r2), v3 = h4_to_f4(r3);
            s0.x += v0.x; s0.y += v0.y; s0.z += v0.z; s0.w += v0.w;
            s1.x += v1.x; s1.y += v1.y; s1.z += v1.z; s1.w += v1.w;
            s2.x += v2.x; s2.y += v2.y; s2.z += v2.z; s2.w += v2.w;
            s3.x += v3.x; s3.y += v3.y; s3.z += v3.z; s3.w += v3.w;
        }
        for (; i < end; i++) {
            float4 v = h4_to_f4(*(const uint2*)&g1[(size_t)d_src[i] * HIDDEN + ch]);
            s0.x += v.x; s0.y += v.y; s0.z += v.z; s0.w += v.w;
        }
        s0.x += s1.x + s2.x + s3.x;
        s0.y += s1.y + s2.y + s3.y;
        s0.z += s1.z + s2.z + s3.z;
        s0.w += s1.w + s2.w + s3.w;
        di = d_dinv[n];
        float4 bb = *(const float4*)&b1[lane * 4];
        float* xr = &x1s[local * X1_STRIDE + lane * 4];
        xr[0] = fmaxf(di * s0.x + bb.x, 0.f);
        xr[1] = fmaxf(di * s0.y + bb.y, 0.f);
        xr[2] = fmaxf(di * s0.z + bb.z, 0.f);
        xr[3] = fmaxf(di * s0.w + bb.w, 0.f);
    }
    __syncthreads();

    if (!alive) return;
    const float* xr = &x1s[local * X1_STRIDE];
    const float* wr = &w2t[lane * W2T_STRIDE];
    float acc = 0.f;
    #pragma unroll
    for (int k = 0; k < HIDDEN; k += 4) {
        float4 x = *(const float4*)&xr[k];       // broadcast across 16 lanes
        acc += x.x * wr[k + 0];
        acc += x.y * wr[k + 1];
        acc += x.z * wr[k + 2];
        acc += x.w * wr[k + 3];
    }
    d_g2[n * LOC_OUT + lane] = di * acc;         // fully coalesced
}

// ---------------- layer-2 aggregate:  x2 = dinv*(sum+self) + b2 --------------
__global__ __launch_bounds__(256) void k_agg2(const float* __restrict__ b2) {
    int tid = threadIdx.x;
    int lane = tid & 3;
    int n = blockIdx.x * 64 + (tid >> 2);
    if (n >= N_NODES) return;

    const float4* g2 = (const float4*)d_g2;
    float4 s0 = g2[n * 4 + lane];                // self loop term
    float4 s1 = make_float4(0.f, 0.f, 0.f, 0.f);
    float4 s2 = make_float4(0.f, 0.f, 0.f, 0.f);
    float4 s3 = make_float4(0.f, 0.f, 0.f, 0.f);
    int beg = d_off[n], end = d_off[n + 1];
    int i = beg;
    for (; i + 3 < end; i += 4) {
        int a0 = d_src[i],     a1 = d_src[i + 1];
        int a2 = d_src[i + 2], a3 = d_src[i + 3];
        float4 v0 = g2[a0 * 4 + lane];
        float4 v1 = g2[a1 * 4 + lane];
        float4 v2 = g2[a2 * 4 + lane];
        float4 v3 = g2[a3 * 4 + lane];
        s0.x += v0.x; s0.y += v0.y; s0.z += v0.z; s0.w += v0.w;
        s1.x += v1.x; s1.y += v1.y; s1.z += v1.z; s1.w += v1.w;
        s2.x += v2.x; s2.y += v2.y; s2.z += v2.z; s2.w += v2.w;
        s3.x += v3.x; s3.y += v3.y; s3.z += v3.z; s3.w += v3.w;
    }
    for (; i < end; i++) {
        float4 v = g2[d_src[i] * 4 + lane];
        s0.x += v.x; s0.y += v.y; s0.z += v.z; s0.w += v.w;
    }
    s0.x += s1.x + s2.x + s3.x;
    s0.y += s1.y + s2.y + s3.y;
    s0.z += s1.z + s2.z + s3.z;
    s0.w += s1.w + s2.w + s3.w;
    float di = d_dinv[n];
    float4 bb = *(const float4*)&b2[lane * 4];
    float4 r;
    r.x = di * s0.x + bb.x;
    r.y = di * s0.y + bb.y;
    r.z = di * s0.z + bb.z;
    r.w = di * s0.w + bb.w;
    ((float4*)d_x2)[n * 4 + lane] = r;
}

// ---------------- final: attention pool over {x2, glob} + linear head --------
__global__ __launch_bounds__(256) void k_final(const float* __restrict__ glob,
                                               const float* __restrict__ aw1,
                                               const float* __restrict__ ab1,
                                               const float* __restrict__ aw2,
                                               const float* __restrict__ lw,
                                               const float* __restrict__ lb,
                                               float* __restrict__ out) {
    __shared__ float s_aw1[256], s_ab1[16], s_aw2[16];
    __shared__ float s_lw[LOC_OUT * OUT_CH], s_lb[OUT_CH];
    int tid = threadIdx.x;
    if (tid < 256) s_aw1[tid] = aw1[tid];
    if (tid < 16) { s_ab1[tid] = ab1[tid]; s_aw2[tid] = aw2[tid]; }
    for (int i = tid; i < LOC_OUT * OUT_CH; i += 256) s_lw[i] = lw[i];
    if (tid < OUT_CH) s_lb[tid] = lb[tid];
    __syncthreads();

    int n = blockIdx.x * 256 + tid;
    if (n >= N_NODES) return;
    float z0[16], z1[16];
    const float4* x2 = (const float4*)&d_x2[n * LOC_OUT];
    const float4* gl = (const float4*)&glob[n * LOC_OUT];
    #pragma unroll
    for (int q = 0; q < 4; q++) {
        float4 a = x2[q], e = gl[q];
        z0[q*4+0] = a.x; z0[q*4+1] = a.y; z0[q*4+2] = a.z; z0[q*4+3] = a.w;
        z1[q*4+0] = e.x; z1[q*4+1] = e.y; z1[q*4+2] = e.z; z1[q*4+3] = e.w;
    }
    float w0 = 0.f, w1 = 0.f;
    #pragma unroll
    for (int j = 0; j < 16; j++) {
        float s0 = s_ab1[j], s1 = s_ab1[j];
        #pragma unroll
        for (int i2 = 0; i2 < 16; i2++) {
            s0 += z0[i2] * s_aw1[i2 * 16 + j];
            s1 += z1[i2] * s_aw1[i2 * 16 + j];
        }
        w0 += tanhf(s0) * s_aw2[j];
        w1 += tanhf(s1) * s_aw2[j];
    }
    float beta0 = 1.f / (1.f + expf(w1 - w0));   // softmax over 2 slots
    float beta1 = 1.f - beta0;
    float emb[16];
    #pragma unroll
    for (int i2 = 0; i2 < 16; i2++) emb[i2] = beta0 * z0[i2] + beta1 * z1[i2];
    #pragma unroll
    for (int j = 0; j < OUT_CH; j++) {
        float o = s_lb[j];
        #pragma unroll
        for (int i2 = 0; i2 < 16; i2++) o += emb[i2] * s_lw[i2 * OUT_CH + j];
        out[(size_t)n * OUT_CH + j] = o;
    }
}

// ---------------- launch ------------------------------------------------------
extern "C" void kernel_launch(void* const* d_in, const int* in_sizes, int n_in,
                              void* d_out, int out_size) {
    const float* X    = (const float*)d_in[0];
    const void*  ei   = d_in[1];
    const float* glob = (const float*)d_in[2];
    const float* W1   = (const float*)d_in[3];
    const float* b1   = (const float*)d_in[4];
    const float* W2   = (const float*)d_in[5];
    const float* b2   = (const float*)d_in[6];
    const float* aw1  = (const float*)d_in[7];
    const float* ab1  = (const float*)d_in[8];
    const float* aw2  = (const float*)d_in[9];
    const float* lw   = (const float*)d_in[10];
    const float* lb   = (const float*)d_in[11];
    float* out = (float*)d_out;

    k_init  <<<(N_NODES + 255) / 256, 256>>>();                 // 0
    k_detect<<<1, 256>>>((const int*)ei);                       // 1
    k_count <<<(N_EDGES + 255) / 256, 256>>>(ei);               // 2
    k_gemm1 <<<(N_NODES + 127) / 128, 256>>>(X, W1);            // 3  <- profiled
    k_scan  <<<1, 1024>>>();                                    // 4
    k_place <<<(N_EDGES + 255) / 256, 256>>>(ei);               // 5
    k_aggmid<<<(N_NODES + 15) / 16, 256>>>(b1, W2);             // 6
    k_agg2  <<<(N_NODES + 63) / 64, 256>>>(b2);                 // 7
    k_final <<<(N_NODES + 255) / 256, 256>>>(glob, aw1, ab1, aw2, lw, lb, out);  // 8
}

// round 15
// speedup vs baseline: 1.5069x; 1.0201x over previous
#include <cuda_runtime.h>
#include <cuda_bf16.h>
#include <cuda_fp16.h>
#include <cstdint>

#define N_NODES 100000
#define N_EDGES 3200000
#define IN_CH   512
#define HIDDEN  64
#define LOC_OUT 16
#define OUT_CH  40

// ---------------- scratch (static device globals; no runtime alloc) ----------
__device__ __align__(16) int    d_degi[N_NODES];            // edge in-degree
__device__ __align__(16) float  d_dinv[N_NODES];            // 1/sqrt(deg+1)
__device__ __align__(16) __half d_g1  [N_NODES * HIDDEN];   // fp16: dinv*(X@W1)
__device__ __align__(16) __half d_x1  [N_NODES * HIDDEN];   // fp16: relu layer-1 out
__device__ __align__(16) __half d_g2h [N_NODES * LOC_OUT];  // fp16: dinv*(x1@W2)
__device__ __align__(16) float  d_x2  [N_NODES * LOC_OUT];  // layer-2 output (z0)
__device__ __align__(16) int    d_off [N_NODES + 1];        // CSR offsets (by dst)
__device__ __align__(16) int    d_cur [N_NODES];            // placement cursors
__device__ __align__(16) int    d_src [N_EDGES];            // dst-sorted source ids
__device__ int d_idx_nonzero_odd;   // >0  =>  edge_index is int32

// ---------------- edge index fetch: handles int64 or int32 buffers -----------
__device__ __forceinline__ int load_edge(const void* ei, unsigned int pos) {
    if (d_idx_nonzero_odd == 0) {          // int64 payload (high words all 0)
        return (int)((const long long*)ei)[pos];
    } else {                               // int32 payload
        return ((const int*)ei)[pos];
    }
}

// ---------------- fp16 quad -> float4 ----------------------------------------
__device__ __forceinline__ float4 h4_to_f4(uint2 r) {
    __half2 a = *reinterpret_cast<__half2*>(&r.x);
    __half2 b = *reinterpret_cast<__half2*>(&r.y);
    float2 fa = __half22float2(a), fb = __half22float2(b);
    return make_float4(fa.x, fa.y, fb.x, fb.y);
}

// ---------------- dtype detection: sample odd int32 slots --------------------
__global__ void k_detect(const int* __restrict__ ei32) {
    int t = threadIdx.x;
    int nz = 0;
    #pragma unroll
    for (int j = 0; j < 8; j++) nz |= ei32[2 * (t * 8 + j) + 1];
    if (nz) atomicOr(&d_idx_nonzero_odd, 1);
}

// ---------------- init: zero degree histogram + flag -------------------------
__global__ void k_init() {
    int i = blockIdx.x * blockDim.x + threadIdx.x;
    if (i < N_NODES) d_degi[i] = 0;
    if (i == 0)      d_idx_nonzero_odd = 0;
}

// ---------------- degree count over targets (col = edge_index[1]) ------------
__global__ void k_count(const void* __restrict__ ei) {
    unsigned int e = blockIdx.x * blockDim.x + threadIdx.x;
    if (e < N_EDGES) {
        int c = load_edge(ei, N_EDGES + e);
        if ((unsigned)c < N_NODES) atomicAdd(&d_degi[c], 1);
    }
}

// ================= mma.sync GEMM1:  g1 = dinv * (X @ W1)  (fp16 out) =========
#define SWZ(o) ((o) ^ (((o) >> 3) & 0x70))
#define KC 64

__device__ __forceinline__ uint32_t smem_u32(const void* p) {
    uint32_t a;
    asm("{ .reg .u64 t; cvta.to.shared.u64 t, %1; cvt.u32.u64 %0, t; }"
        : "=r"(a) : "l"(p));
    return a;
}
__device__ __forceinline__ void ldsm_x4(uint32_t* r, uint32_t addr) {
    asm volatile("ldmatrix.sync.aligned.m8n8.x4.shared.b16 {%0,%1,%2,%3}, [%4];"
                 : "=r"(r[0]), "=r"(r[1]), "=r"(r[2]), "=r"(r[3]) : "r"(addr));
}
__device__ __forceinline__ void ldsm_x4_t(uint32_t* r, uint32_t addr) {
    asm volatile("ldmatrix.sync.aligned.m8n8.x4.trans.shared.b16 {%0,%1,%2,%3}, [%4];"
                 : "=r"(r[0]), "=r"(r[1]), "=r"(r[2]), "=r"(r[3]) : "r"(addr));
}
__device__ __forceinline__ void mma16816(float* c, const uint32_t* a,
                                         uint32_t b0, uint32_t b1) {
    asm volatile(
        "mma.sync.aligned.m16n8k16.row.col.f32.bf16.bf16.f32 "
        "{%0,%1,%2,%3}, {%4,%5,%6,%7}, {%8,%9}, {%0,%1,%2,%3};"
        : "+f"(c[0]), "+f"(c[1]), "+f"(c[2]), "+f"(c[3])
        : "r"(a[0]), "r"(a[1]), "r"(a[2]), "r"(a[3]), "r"(b0), "r"(b1));
}
__device__ __forceinline__ uint32_t pack_bf16x2(float a, float b) {
    uint32_t r;
    asm("cvt.rn.bf16x2.f32 %0, %1, %2;" : "=r"(r) : "f"(b), "f"(a));
    return r;
}

__global__ __launch_bounds__(256, 2) void k_gemm1(const float* __restrict__ X,
                                                  const float* __restrict__ W1) {
    __shared__ __align__(16) char sAh[128 * 128];   // 16 KB
    __shared__ __align__(16) char sAl[128 * 128];   // 16 KB
    __shared__ __align__(16) char sBh[KC * 128];    // 8 KB
    __shared__ __align__(16) char sBl[KC * 128];    // 8 KB
    int tid = threadIdx.x;
    int wid = tid >> 5, lane = tid & 31;
    int row0 = blockIdx.x * 128;
    int wr0 = wid * 16;

    float acc[8][4];
    #pragma unroll
    for (int i = 0; i < 8; i++)
        #pragma unroll
        for (int j = 0; j < 4; j++) acc[i][j] = 0.f;

    uint32_t aAh = smem_u32(sAh), aAl = smem_u32(sAl);
    uint32_t aBh = smem_u32(sBh), aBl = smem_u32(sBl);

    uint32_t a_row = (uint32_t)(wr0 + (lane & 15));
    uint32_t a_kh  = (uint32_t)((lane >> 4) * 16);
    uint32_t b_krow = (uint32_t)((lane & 7) + ((lane >> 3) & 1) * 8);
    uint32_t b_nh   = (uint32_t)((lane >> 4) * 16);

    for (int c = 0; c < IN_CH / KC; c++) {
        int k0 = c * KC;
        #pragma unroll
        for (int it = 0; it < 8; it++) {
            int idx = it * 256 + tid;
            int row = idx >> 4;
            int kq = (idx & 15) * 4;
            int gr = row0 + row;
            float4 v = (gr < N_NODES)
                     ? *(const float4*)&X[(size_t)gr * IN_CH + k0 + kq]
                     : make_float4(0.f, 0.f, 0.f, 0.f);
            uint32_t h0 = pack_bf16x2(v.x, v.y);
            uint32_t h1 = pack_bf16x2(v.z, v.w);
            float lx = v.x - __bfloat162float(__ushort_as_bfloat16((unsigned short)(h0 & 0xFFFF)));
            float ly = v.y - __bfloat162float(__ushort_as_bfloat16((unsigned short)(h0 >> 16)));
            float lz = v.z - __bfloat162float(__ushort_as_bfloat16((unsigned short)(h1 & 0xFFFF)));
            float lw = v.w - __bfloat162float(__ushort_as_bfloat16((unsigned short)(h1 >> 16)));
            uint32_t l0 = pack_bf16x2(lx, ly);
            uint32_t l1 = pack_bf16x2(lz, lw);
            uint32_t o = SWZ((uint32_t)(row * 128 + kq * 2));
            *(uint2*)(sAh + o) = make_uint2(h0, h1);
            *(uint2*)(sAl + o) = make_uint2(l0, l1);
        }
        #pragma unroll
        for (int it = 0; it < 4; it++) {
            int idx = it * 256 + tid;
            int kk = idx >> 4;
            int n0 = (idx & 15) * 4;
            float4 v = *(const float4*)&W1[(size_t)(k0 + kk) * HIDDEN + n0];
            uint32_t h0 = pack_bf16x2(v.x, v.y);
            uint32_t h1 = pack_bf16x2(v.z, v.w);
            float lx = v.x - __bfloat162float(__ushort_as_bfloat16((unsigned short)(h0 & 0xFFFF)));
            float ly = v.y - __bfloat162float(__ushort_as_bfloat16((unsigned short)(h0 >> 16)));
            float lz = v.z - __bfloat162float(__ushort_as_bfloat16((unsigned short)(h1 & 0xFFFF)));
            float lw = v.w - __bfloat162float(__ushort_as_bfloat16((unsigned short)(h1 >> 16)));
            uint32_t l0 = pack_bf16x2(lx, ly);
            uint32_t l1 = pack_bf16x2(lz, lw);
            uint32_t o = SWZ((uint32_t)(kk * 128 + n0 * 2));
            *(uint2*)(sBh + o) = make_uint2(h0, h1);
            *(uint2*)(sBl + o) = make_uint2(l0, l1);
        }
        __syncthreads();

        #pragma unroll
        for (int k16 = 0; k16 < KC / 16; k16++) {
            uint32_t ao = SWZ(a_row * 128 + (uint32_t)k16 * 32 + a_kh);
            uint32_t ah[4], al[4];
            ldsm_x4(ah, aAh + ao);
            ldsm_x4(al, aAl + ao);
            #pragma unroll
            for (int p = 0; p < 4; p++) {
                uint32_t bo = SWZ(((uint32_t)k16 * 16 + b_krow) * 128
                                  + (uint32_t)p * 32 + b_nh);
                uint32_t bh[4], bl[4];
                ldsm_x4_t(bh, aBh + bo);
                ldsm_x4_t(bl, aBl + bo);
                mma16816(acc[2 * p],     ah, bh[0], bh[1]);
                mma16816(acc[2 * p],     ah, bl[0], bl[1]);
                mma16816(acc[2 * p],     al, bh[0], bh[1]);
                mma16816(acc[2 * p + 1], ah, bh[2], bh[3]);
                mma16816(acc[2 * p + 1], ah, bl[2], bl[3]);
                mma16816(acc[2 * p + 1], al, bh[2], bh[3]);
            }
        }
        __syncthreads();
    }

    // ---- epilogue: scale by dinv, convert to fp16, store; persist dinv ------
    int gid = lane >> 2, tig = lane & 3;
    int r0 = row0 + wr0 + gid;
    int r1 = r0 + 8;
    float di0 = 0.f, di1 = 0.f;
    if (r0 < N_NODES) di0 = rsqrtf((float)(d_degi[r0] + 1));
    if (r1 < N_NODES) di1 = rsqrtf((float)(d_degi[r1] + 1));
    if (tig == 0) {
        if (r0 < N_NODES) d_dinv[r0] = di0;
        if (r1 < N_NODES) d_dinv[r1] = di1;
    }
    #pragma unroll
    for (int nt = 0; nt < 8; nt++) {
        int col = nt * 8 + tig * 2;
        if (r0 < N_NODES)
            *(__half2*)&d_g1[(size_t)r0 * HIDDEN + col] =
                __floats2half2_rn(di0 * acc[nt][0], di0 * acc[nt][1]);
        if (r1 < N_NODES)
            *(__half2*)&d_g1[(size_t)r1 * HIDDEN + col] =
                __floats2half2_rn(di1 * acc[nt][2], di1 * acc[nt][3]);
    }
}

// ---------------- exclusive scan of degrees -> CSR offsets (1 block) ---------
__global__ __launch_bounds__(1024) void k_scan() {
    __shared__ int s[1024];
    const int C = (N_NODES + 1023) / 1024;       // 98
    int t = threadIdx.x;
    int beg = t * C;
    int end = beg + C; if (end > N_NODES) end = N_NODES;
    int loc = 0;
    for (int i = beg; i < end; i++) loc += d_degi[i];
    s[t] = loc;
    __syncthreads();
    for (int o = 1; o < 1024; o <<= 1) {
        int v = (t >= o) ? s[t - o] : 0;
        __syncthreads();
        s[t] += v;
        __syncthreads();
    }
    int run = (t > 0) ? s[t - 1] : 0;
    for (int i = beg; i < end; i++) {
        d_off[i] = run;
        d_cur[i] = run;
        run += d_degi[i];
    }
    if (t == 1023) d_off[N_NODES] = s[1023];
}

// ---------------- place edges into dst-sorted source list --------------------
__global__ void k_place(const void* __restrict__ ei) {
    unsigned int e = blockIdx.x * blockDim.x + threadIdx.x;
    if (e >= N_EDGES) return;
    int r = load_edge(ei, e);
    int c = load_edge(ei, N_EDGES + e);
    if ((unsigned)r >= N_NODES || (unsigned)c >= N_NODES) return;
    int pos = atomicAdd(&d_cur[c], 1);
    d_src[pos] = r;
}

// ---------------- layer-1 aggregate + relu (no block barrier) ----------------
// 16 lanes per node, 2 nodes per warp; writes x1 as fp16.
__global__ __launch_bounds__(256) void k_agg1(const float* __restrict__ b1) {
    int g = blockIdx.x * 256 + threadIdx.x;
    int lane = g & 15;
    int n = g >> 4;
    if (n >= N_NODES) return;

    const __half* g1 = d_g1;
    size_t ch = (size_t)lane * 4;
    float4 s0 = h4_to_f4(*(const uint2*)&g1[(size_t)n * HIDDEN + ch]);  // self
    float4 s1 = make_float4(0.f, 0.f, 0.f, 0.f);
    float4 s2 = make_float4(0.f, 0.f, 0.f, 0.f);
    float4 s3 = make_float4(0.f, 0.f, 0.f, 0.f);
    int beg = d_off[n], end = d_off[n + 1];
    int i = beg;
    for (; i + 3 < end; i += 4) {
        int a0 = d_src[i],     a1 = d_src[i + 1];
        int a2 = d_src[i + 2], a3 = d_src[i + 3];
        uint2 r0 = *(const uint2*)&g1[(size_t)a0 * HIDDEN + ch];
        uint2 r1 = *(const uint2*)&g1[(size_t)a1 * HIDDEN + ch];
        uint2 r2 = *(const uint2*)&g1[(size_t)a2 * HIDDEN + ch];
        uint2 r3 = *(const uint2*)&g1[(size_t)a3 * HIDDEN + ch];
        float4 v0 = h4_to_f4(r0), v1 = h4_to_f4(r1);
        float4 v2 = h4_to_f4(r2), v3 = h4_to_f4(r3);
        s0.x += v0.x; s0.y += v0.y; s0.z += v0.z; s0.w += v0.w;
        s1.x += v1.x; s1.y += v1.y; s1.z += v1.z; s1.w += v1.w;
        s2.x += v2.x; s2.y += v2.y; s2.z += v2.z; s2.w += v2.w;
        s3.x += v3.x; s3.y += v3.y; s3.z += v3.z; s3.w += v3.w;
    }
    for (; i < end; i++) {
        float4 v = h4_to_f4(*(const uint2*)&g1[(size_t)d_src[i] * HIDDEN + ch]);
        s0.x += v.x; s0.y += v.y; s0.z += v.z; s0.w += v.w;
    }
    s0.x += s1.x + s2.x + s3.x;
    s0.y += s1.y + s2.y + s3.y;
    s0.z += s1.z + s2.z + s3.z;
    s0.w += s1.w + s2.w + s3.w;
    float di = d_dinv[n];
    float4 bb = *(const float4*)&b1[lane * 4];
    __half2 h0 = __floats2half2_rn(fmaxf(di * s0.x + bb.x, 0.f),
                                   fmaxf(di * s0.y + bb.y, 0.f));
    __half2 h1 = __floats2half2_rn(fmaxf(di * s0.z + bb.z, 0.f),
                                   fmaxf(di * s0.w + bb.w, 0.f));
    uint2 o;
    o.x = *reinterpret_cast<uint32_t*>(&h0);
    o.y = *reinterpret_cast<uint32_t*>(&h1);
    *(uint2*)&d_x1[(size_t)n * HIDDEN + ch] = o;
}

// ---------------- g2 = dinv*(x1 @ W2), dense, 1 thread/node, fp16 out --------
#define W2T_STRIDE 65
__global__ __launch_bounds__(256) void k_mid(const float* __restrict__ W2) {
    __shared__ float w2t[LOC_OUT * W2T_STRIDE];  // w2t[j*65+k] = W2[k*16+j]
    int tid = threadIdx.x;
    for (int i = tid; i < HIDDEN * LOC_OUT; i += 256) {
        int k = i >> 4, j = i & 15;
        w2t[j * W2T_STRIDE + k] = W2[i];
    }
    __syncthreads();

    int n = blockIdx.x * 256 + tid;
    if (n >= N_NODES) return;

    float acc[LOC_OUT];
    #pragma unroll
    for (int j = 0; j < LOC_OUT; j++) acc[j] = 0.f;

    const uint4* xr = (const uint4*)&d_x1[(size_t)n * HIDDEN];
    #pragma unroll
    for (int u = 0; u < 4; u++) {                // 4 x uint4 = 32 halves... (2 per u-half)
        uint4 r = xr[u];
        float f[8];
        {
            float2 p;
            p = __half22float2(*reinterpret_cast<__half2*>(&r.x)); f[0]=p.x; f[1]=p.y;
            p = __half22float2(*reinterpret_cast<__half2*>(&r.y)); f[2]=p.x; f[3]=p.y;
            p = __half22float2(*reinterpret_cast<__half2*>(&r.z)); f[4]=p.x; f[5]=p.y;
            p = __half22float2(*reinterpret_cast<__half2*>(&r.w)); f[6]=p.x; f[7]=p.y;
        }
        #pragma unroll
        for (int kk = 0; kk < 8; kk++) {
            float x = f[kk];
            int kb = u * 8 + kk;
            #pragma unroll
            for (int j = 0; j < LOC_OUT; j++)
                acc[j] += x * w2t[j * W2T_STRIDE + kb];
        }
    }
    // second half: halves 32..63 (next 2 uint4)
    #pragma unroll
    for (int u = 4; u < 8; u++) {
        uint4 r = ((const uint4*)&d_x1[(size_t)n * HIDDEN])[u & 3];  // placeholder
    }
    // NOTE: HIDDEN=64 halves = 128 bytes = 8 uint4; handle remaining 4:
    #pragma unroll
    for (int u = 4; u < 8; u++) {
        uint4 r = xr[u];
        float f[8];
        {
            float2 p;
            p = __half22float2(*reinterpret_cast<__half2*>(&r.x)); f[0]=p.x; f[1]=p.y;
            p = __half22float2(*reinterpret_cast<__half2*>(&r.y)); f[2]=p.x; f[3]=p.y;
            p = __half22float2(*reinterpret_cast<__half2*>(&r.z)); f[4]=p.x; f[5]=p.y;
            p = __half22float2(*reinterpret_cast<__half2*>(&r.w)); f[6]=p.x; f[7]=p.y;
        }
        #pragma unroll
        for (int kk = 0; kk < 8; kk++) {
            float x = f[kk];
            int kb = u * 8 + kk;
            #pragma unroll
            for (int j = 0; j < LOC_OUT; j++)
                acc[j] += x * w2t[j * W2T_STRIDE + kb];
        }
    }

    float di = d_dinv[n];
    uint4 o0, o1;
    __half2 h;
    h = __floats2half2_rn(di*acc[0],  di*acc[1]);  o0.x = *reinterpret_cast<uint32_t*>(&h);
    h = __floats2half2_rn(di*acc[2],  di*acc[3]);  o0.y = *reinterpret_cast<uint32_t*>(&h);
    h = __floats2half2_rn(di*acc[4],  di*acc[5]);  o0.z = *reinterpret_cast<uint32_t*>(&h);
    h = __floats2half2_rn(di*acc[6],  di*acc[7]);  o0.w = *reinterpret_cast<uint32_t*>(&h);
    h = __floats2half2_rn(di*acc[8],  di*acc[9]);  o1.x = *reinterpret_cast<uint32_t*>(&h);
    h = __floats2half2_rn(di*acc[10], di*acc[11]); o1.y = *reinterpret_cast<uint32_t*>(&h);
    h = __floats2half2_rn(di*acc[12], di*acc[13]); o1.z = *reinterpret_cast<uint32_t*>(&h);
    h = __floats2half2_rn(di*acc[14], di*acc[15]); o1.w = *reinterpret_cast<uint32_t*>(&h);
    uint4* dst = (uint4*)&d_g2h[(size_t)n * LOC_OUT];
    dst[0] = o0;
    dst[1] = o1;
}

// ---------------- layer-2 aggregate (fp16 gather):  x2 = dinv*sum + b2 -------
__global__ __launch_bounds__(256) void k_agg2(const float* __restrict__ b2) {
    int tid = threadIdx.x;
    int lane = tid & 3;
    int n = blockIdx.x * 64 + (tid >> 2);
    if (n >= N_NODES) return;

    const __half* g2 = d_g2h;
    size_t ch = (size_t)lane * 4;
    float4 s0 = h4_to_f4(*(const uint2*)&g2[(size_t)n * LOC_OUT + ch]);  // self
    float4 s1 = make_float4(0.f, 0.f, 0.f, 0.f);
    float4 s2 = make_float4(0.f, 0.f, 0.f, 0.f);
    float4 s3 = make_float4(0.f, 0.f, 0.f, 0.f);
    int beg = d_off[n], end = d_off[n + 1];
    int i = beg;
    for (; i + 3 < end; i += 4) {
        int a0 = d_src[i],     a1 = d_src[i + 1];
        int a2 = d_src[i + 2], a3 = d_src[i + 3];
        float4 v0 = h4_to_f4(*(const uint2*)&g2[(size_t)a0 * LOC_OUT + ch]);
        float4 v1 = h4_to_f4(*(const uint2*)&g2[(size_t)a1 * LOC_OUT + ch]);
        float4 v2 = h4_to_f4(*(const uint2*)&g2[(size_t)a2 * LOC_OUT + ch]);
        float4 v3 = h4_to_f4(*(const uint2*)&g2[(size_t)a3 * LOC_OUT + ch]);
        s0.x += v0.x; s0.y += v0.y; s0.z += v0.z; s0.w += v0.w;
        s1.x += v1.x; s1.y += v1.y; s1.z += v1.z; s1.w += v1.w;
        s2.x += v2.x; s2.y += v2.y; s2.z += v2.z; s2.w += v2.w;
        s3.x += v3.x; s3.y += v3.y; s3.z += v3.z; s3.w += v3.w;
    }
    for (; i < end; i++) {
        float4 v = h4_to_f4(*(const uint2*)&g2[(size_t)d_src[i] * LOC_OUT + ch]);
        s0.x += v.x; s0.y += v.y; s0.z += v.z; s0.w += v.w;
    }
    s0.x += s1.x + s2.x + s3.x;
    s0.y += s1.y + s2.y + s3.y;
    s0.z += s1.z + s2.z + s3.z;
    s0.w += s1.w + s2.w + s3.w;
    float di = d_dinv[n];
    float4 bb = *(const float4*)&b2[lane * 4];
    float4 r;
    r.x = di * s0.x + bb.x;
    r.y = di * s0.y + bb.y;
    r.z = di * s0.z + bb.z;
    r.w = di * s0.w + bb.w;
    ((float4*)d_x2)[n * 4 + lane] = r;
}

// ---------------- final: attention pool over {x2, glob} + linear head --------
__global__ __launch_bounds__(256) void k_final(const float* __restrict__ glob,
                                               const float* __restrict__ aw1,
                                               const float* __restrict__ ab1,
                                               const float* __restrict__ aw2,
                                               const float* __restrict__ lw,
                                               const float* __restrict__ lb,
                                               float* __restrict__ out) {
    __shared__ float s_aw1[256], s_ab1[16], s_aw2[16];
    __shared__ float s_lw[LOC_OUT * OUT_CH], s_lb[OUT_CH];
    int tid = threadIdx.x;
    if (tid < 256) s_aw1[tid] = aw1[tid];
    if (tid < 16) { s_ab1[tid] = ab1[tid]; s_aw2[tid] = aw2[tid]; }
    for (int i = tid; i < LOC_OUT * OUT_CH; i += 256) s_lw[i] = lw[i];
    if (tid < OUT_CH) s_lb[tid] = lb[tid];
    __syncthreads();

    int n = blockIdx.x * 256 + tid;
    if (n >= N_NODES) return;
    float z0[16], z1[16];
    const float4* x2 = (const float4*)&d_x2[n * LOC_OUT];
    const float4* gl = (const float4*)&glob[n * LOC_OUT];
    #pragma unroll
    for (int q = 0; q < 4; q++) {
        float4 a = x2[q], e = gl[q];
        z0[q*4+0] = a.x; z0[q*4+1] = a.y; z0[q*4+2] = a.z; z0[q*4+3] = a.w;
        z1[q*4+0] = e.x; z1[q*4+1] = e.y; z1[q*4+2] = e.z; z1[q*4+3] = e.w;
    }
    float w0 = 0.f, w1 = 0.f;
    #pragma unroll
    for (int j = 0; j < 16; j++) {
        float s0 = s_ab1[j], s1 = s_ab1[j];
        #pragma unroll
        for (int i2 = 0; i2 < 16; i2++) {
            s0 += z0[i2] * s_aw1[i2 * 16 + j];
            s1 += z1[i2] * s_aw1[i2 * 16 + j];
        }
        w0 += tanhf(s0) * s_aw2[j];
        w1 += tanhf(s1) * s_aw2[j];
    }
    float beta0 = 1.f / (1.f + expf(w1 - w0));   // softmax over 2 slots
    float beta1 = 1.f - beta0;
    float emb[16];
    #pragma unroll
    for (int i2 = 0; i2 < 16; i2++) emb[i2] = beta0 * z0[i2] + beta1 * z1[i2];
    #pragma unroll
    for (int j = 0; j < OUT_CH; j++) {
        float o = s_lb[j];
        #pragma unroll
        for (int i2 = 0; i2 < 16; i2++) o += emb[i2] * s_lw[i2 * OUT_CH + j];
        out[(size_t)n * OUT_CH + j] = o;
    }
}

// ---------------- launch ------------------------------------------------------
extern "C" void kernel_launch(void* const* d_in, const int* in_sizes, int n_in,
                              void* d_out, int out_size) {
    const float* X    = (const float*)d_in[0];
    const void*  ei   = d_in[1];
    const float* glob = (const float*)d_in[2];
    const float* W1   = (const float*)d_in[3];
    const float* b1   = (const float*)d_in[4];
    const float* W2   = (const float*)d_in[5];
    const float* b2   = (const float*)d_in[6];
    const float* aw1  = (const float*)d_in[7];
    const float* ab1  = (const float*)d_in[8];
    const float* aw2  = (const float*)d_in[9];
    const float* lw   = (const float*)d_in[10];
    const float* lb   = (const float*)d_in[11];
    float* out = (float*)d_out;

    k_init  <<<(N_NODES + 255) / 256, 256>>>();                 // 0
    k_detect<<<1, 256>>>((const int*)ei);                       // 1
    k_count <<<(N_EDGES + 255) / 256, 256>>>(ei);               // 2
    k_gemm1 <<<(N_NODES + 127) / 128, 256>>>(X, W1);            // 3  <- profiled
    k_scan  <<<1, 1024>>>();                                    // 4
    k_place <<<(N_EDGES + 255) / 256, 256>>>(ei);               // 5
    k_agg1  <<<(N_NODES * 16 + 255) / 256, 256>>>(b1);          // 6
    k_mid   <<<(N_NODES + 255) / 256, 256>>>(W2);               // 7
    k_agg2  <<<(N_NODES + 63) / 64, 256>>>(b2);                 // 8
    k_final <<<(N_NODES + 255) / 256, 256>>>(glob, aw1, ab1, aw2, lw, lb, out);  // 9
}

// round 16
// speedup vs baseline: 2.5496x; 1.6919x over previous
#include <cuda_runtime.h>
#include <cuda_bf16.h>
#include <cuda_fp16.h>
#include <cstdint>

#define N_NODES 100000
#define N_EDGES 3200000
#define IN_CH   512
#define HIDDEN  64
#define LOC_OUT 16
#define OUT_CH  40
#define NSCB    98          // scan blocks: ceil(100000/1024)

// ---------------- scratch (static device globals; no runtime alloc) ----------
__device__ __align__(16) int    d_degi[N_NODES];            // edge in-degree
__device__ __align__(16) float  d_dinv[N_NODES];            // 1/sqrt(deg+1)
__device__ __align__(16) __half d_g1  [N_NODES * HIDDEN];   // fp16: dinv*(X@W1)
__device__ __align__(16) __half d_x1  [N_NODES * HIDDEN];   // fp16: relu layer-1 out
__device__ __align__(16) __half d_g2h [N_NODES * LOC_OUT];  // fp16: dinv*(x1@W2)
__device__ __align__(16) float  d_x2  [N_NODES * LOC_OUT];  // layer-2 output (z0)
__device__ __align__(16) int    d_off [N_NODES + 1];        // CSR offsets (by dst)
__device__ __align__(16) int    d_cur [N_NODES];            // placement cursors
__device__ __align__(16) int    d_src [N_EDGES];            // dst-sorted source ids
__device__ __align__(16) int    d_blk [NSCB];               // scan: block totals
__device__ __align__(16) int    d_blkoff[NSCB];             // scan: block offsets
__device__ int d_idx_nonzero_odd;   // >0  =>  edge_index is int32

// ---------------- edge index fetch: handles int64 or int32 buffers -----------
__device__ __forceinline__ int load_edge(const void* ei, unsigned int pos) {
    if (d_idx_nonzero_odd == 0) {          // int64 payload (high words all 0)
        return (int)((const long long*)ei)[pos];
    } else {                               // int32 payload
        return ((const int*)ei)[pos];
    }
}

// ---------------- fp16 quad -> float4 ----------------------------------------
__device__ __forceinline__ float4 h4_to_f4(uint2 r) {
    __half2 a = *reinterpret_cast<__half2*>(&r.x);
    __half2 b = *reinterpret_cast<__half2*>(&r.y);
    float2 fa = __half22float2(a), fb = __half22float2(b);
    return make_float4(fa.x, fa.y, fb.x, fb.y);
}

// ---------------- dtype detection: sample odd int32 slots --------------------
__global__ void k_detect(const int* __restrict__ ei32) {
    int t = threadIdx.x;
    int nz = 0;
    #pragma unroll
    for (int j = 0; j < 8; j++) nz |= ei32[2 * (t * 8 + j) + 1];
    if (nz) atomicOr(&d_idx_nonzero_odd, 1);
}

// ---------------- init: zero degree histogram + flag -------------------------
__global__ void k_init() {
    int i = blockIdx.x * blockDim.x + threadIdx.x;
    if (i < N_NODES) d_degi[i] = 0;
    if (i == 0)      d_idx_nonzero_odd = 0;
}

// ---------------- degree count over targets (col = edge_index[1]) ------------
__global__ void k_count(const void* __restrict__ ei) {
    unsigned int e = blockIdx.x * blockDim.x + threadIdx.x;
    if (e < N_EDGES) {
        int c = load_edge(ei, N_EDGES + e);
        if ((unsigned)c < N_NODES) atomicAdd(&d_degi[c], 1);
    }
}

// ================= mma.sync GEMM1:  g1 = dinv * (X @ W1)  (fp16 out) =========
#define SWZ(o) ((o) ^ (((o) >> 3) & 0x70))
#define KC 64

__device__ __forceinline__ uint32_t smem_u32(const void* p) {
    uint32_t a;
    asm("{ .reg .u64 t; cvta.to.shared.u64 t, %1; cvt.u32.u64 %0, t; }"
        : "=r"(a) : "l"(p));
    return a;
}
__device__ __forceinline__ void ldsm_x4(uint32_t* r, uint32_t addr) {
    asm volatile("ldmatrix.sync.aligned.m8n8.x4.shared.b16 {%0,%1,%2,%3}, [%4];"
                 : "=r"(r[0]), "=r"(r[1]), "=r"(r[2]), "=r"(r[3]) : "r"(addr));
}
__device__ __forceinline__ void ldsm_x4_t(uint32_t* r, uint32_t addr) {
    asm volatile("ldmatrix.sync.aligned.m8n8.x4.trans.shared.b16 {%0,%1,%2,%3}, [%4];"
                 : "=r"(r[0]), "=r"(r[1]), "=r"(r[2]), "=r"(r[3]) : "r"(addr));
}
__device__ __forceinline__ void mma16816(float* c, const uint32_t* a,
                                         uint32_t b0, uint32_t b1) {
    asm volatile(
        "mma.sync.aligned.m16n8k16.row.col.f32.bf16.bf16.f32 "
        "{%0,%1,%2,%3}, {%4,%5,%6,%7}, {%8,%9}, {%0,%1,%2,%3};"
        : "+f"(c[0]), "+f"(c[1]), "+f"(c[2]), "+f"(c[3])
        : "r"(a[0]), "r"(a[1]), "r"(a[2]), "r"(a[3]), "r"(b0), "r"(b1));
}
__device__ __forceinline__ uint32_t pack_bf16x2(float a, float b) {
    uint32_t r;
    asm("cvt.rn.bf16x2.f32 %0, %1, %2;" : "=r"(r) : "f"(b), "f"(a));
    return r;
}

__global__ __launch_bounds__(256, 2) void k_gemm1(const float* __restrict__ X,
                                                  const float* __restrict__ W1) {
    __shared__ __align__(16) char sAh[128 * 128];   // 16 KB
    __shared__ __align__(16) char sAl[128 * 128];   // 16 KB
    __shared__ __align__(16) char sBh[KC * 128];    // 8 KB
    __shared__ __align__(16) char sBl[KC * 128];    // 8 KB
    int tid = threadIdx.x;
    int wid = tid >> 5, lane = tid & 31;
    int row0 = blockIdx.x * 128;
    int wr0 = wid * 16;

    float acc[8][4];
    #pragma unroll
    for (int i = 0; i < 8; i++)
        #pragma unroll
        for (int j = 0; j < 4; j++) acc[i][j] = 0.f;

    uint32_t aAh = smem_u32(sAh), aAl = smem_u32(sAl);
    uint32_t aBh = smem_u32(sBh), aBl = smem_u32(sBl);

    uint32_t a_row = (uint32_t)(wr0 + (lane & 15));
    uint32_t a_kh  = (uint32_t)((lane >> 4) * 16);
    uint32_t b_krow = (uint32_t)((lane & 7) + ((lane >> 3) & 1) * 8);
    uint32_t b_nh   = (uint32_t)((lane >> 4) * 16);

    for (int c = 0; c < IN_CH / KC; c++) {
        int k0 = c * KC;
        #pragma unroll
        for (int it = 0; it < 8; it++) {
            int idx = it * 256 + tid;
            int row = idx >> 4;
            int kq = (idx & 15) * 4;
            int gr = row0 + row;
            float4 v = (gr < N_NODES)
                     ? *(const float4*)&X[(size_t)gr * IN_CH + k0 + kq]
                     : make_float4(0.f, 0.f, 0.f, 0.f);
            uint32_t h0 = pack_bf16x2(v.x, v.y);
            uint32_t h1 = pack_bf16x2(v.z, v.w);
            float lx = v.x - __bfloat162float(__ushort_as_bfloat16((unsigned short)(h0 & 0xFFFF)));
            float ly = v.y - __bfloat162float(__ushort_as_bfloat16((unsigned short)(h0 >> 16)));
            float lz = v.z - __bfloat162float(__ushort_as_bfloat16((unsigned short)(h1 & 0xFFFF)));
            float lw = v.w - __bfloat162float(__ushort_as_bfloat16((unsigned short)(h1 >> 16)));
            uint32_t l0 = pack_bf16x2(lx, ly);
            uint32_t l1 = pack_bf16x2(lz, lw);
            uint32_t o = SWZ((uint32_t)(row * 128 + kq * 2));
            *(uint2*)(sAh + o) = make_uint2(h0, h1);
            *(uint2*)(sAl + o) = make_uint2(l0, l1);
        }
        #pragma unroll
        for (int it = 0; it < 4; it++) {
            int idx = it * 256 + tid;
            int kk = idx >> 4;
            int n0 = (idx & 15) * 4;
            float4 v = *(const float4*)&W1[(size_t)(k0 + kk) * HIDDEN + n0];
            uint32_t h0 = pack_bf16x2(v.x, v.y);
            uint32_t h1 = pack_bf16x2(v.z, v.w);
            float lx = v.x - __bfloat162float(__ushort_as_bfloat16((unsigned short)(h0 & 0xFFFF)));
            float ly = v.y - __bfloat162float(__ushort_as_bfloat16((unsigned short)(h0 >> 16)));
            float lz = v.z - __bfloat162float(__ushort_as_bfloat16((unsigned short)(h1 & 0xFFFF)));
            float lw = v.w - __bfloat162float(__ushort_as_bfloat16((unsigned short)(h1 >> 16)));
            uint32_t l0 = pack_bf16x2(lx, ly);
            uint32_t l1 = pack_bf16x2(lz, lw);
            uint32_t o = SWZ((uint32_t)(kk * 128 + n0 * 2));
            *(uint2*)(sBh + o) = make_uint2(h0, h1);
            *(uint2*)(sBl + o) = make_uint2(l0, l1);
        }
        __syncthreads();

        #pragma unroll
        for (int k16 = 0; k16 < KC / 16; k16++) {
            uint32_t ao = SWZ(a_row * 128 + (uint32_t)k16 * 32 + a_kh);
            uint32_t ah[4], al[4];
            ldsm_x4(ah, aAh + ao);
            ldsm_x4(al, aAl + ao);
            #pragma unroll
            for (int p = 0; p < 4; p++) {
                uint32_t bo = SWZ(((uint32_t)k16 * 16 + b_krow) * 128
                                  + (uint32_t)p * 32 + b_nh);
                uint32_t bh[4], bl[4];
                ldsm_x4_t(bh, aBh + bo);
                ldsm_x4_t(bl, aBl + bo);
                mma16816(acc[2 * p],     ah, bh[0], bh[1]);
                mma16816(acc[2 * p],     ah, bl[0], bl[1]);
                mma16816(acc[2 * p],     al, bh[0], bh[1]);
                mma16816(acc[2 * p + 1], ah, bh[2], bh[3]);
                mma16816(acc[2 * p + 1], ah, bl[2], bl[3]);
                mma16816(acc[2 * p + 1], al, bh[2], bh[3]);
            }
        }
        __syncthreads();
    }

    // ---- epilogue: scale by dinv, convert to fp16, store; persist dinv ------
    int gid = lane >> 2, tig = lane & 3;
    int r0 = row0 + wr0 + gid;
    int r1 = r0 + 8;
    float di0 = 0.f, di1 = 0.f;
    if (r0 < N_NODES) di0 = rsqrtf((float)(d_degi[r0] + 1));
    if (r1 < N_NODES) di1 = rsqrtf((float)(d_degi[r1] + 1));
    if (tig == 0) {
        if (r0 < N_NODES) d_dinv[r0] = di0;
        if (r1 < N_NODES) d_dinv[r1] = di1;
    }
    #pragma unroll
    for (int nt = 0; nt < 8; nt++) {
        int col = nt * 8 + tig * 2;
        if (r0 < N_NODES)
            *(__half2*)&d_g1[(size_t)r0 * HIDDEN + col] =
                __floats2half2_rn(di0 * acc[nt][0], di0 * acc[nt][1]);
        if (r1 < N_NODES)
            *(__half2*)&d_g1[(size_t)r1 * HIDDEN + col] =
                __floats2half2_rn(di1 * acc[nt][2], di1 * acc[nt][3]);
    }
}

// ---------------- multi-block exclusive scan of degrees ----------------------
// A: per-block (1024 elems) exclusive intra prefix into d_off, totals to d_blk
__global__ __launch_bounds__(1024) void k_scanA() {
    __shared__ int s[1024];
    int t = threadIdx.x;
    int i = blockIdx.x * 1024 + t;
    int v = (i < N_NODES) ? d_degi[i] : 0;
    s[t] = v;
    __syncthreads();
    for (int o = 1; o < 1024; o <<= 1) {
        int x = (t >= o) ? s[t - o] : 0;
        __syncthreads();
        s[t] += x;
        __syncthreads();
    }
    if (i < N_NODES) d_off[i] = s[t] - v;        // exclusive intra-block
    if (t == 1023) d_blk[blockIdx.x] = s[1023];
}
// B: single block scans the 98 block totals
__global__ __launch_bounds__(128) void k_scanB() {
    __shared__ int s[128];
    int t = threadIdx.x;
    int v = (t < NSCB) ? d_blk[t] : 0;
    s[t] = v;
    __syncthreads();
    for (int o = 1; o < 128; o <<= 1) {
        int x = (t >= o) ? s[t - o] : 0;
        __syncthreads();
        s[t] += x;
        __syncthreads();
    }
    if (t < NSCB) d_blkoff[t] = s[t] - v;        // exclusive
    if (t == 127) d_off[N_NODES] = s[127];
}
// C: add block offsets; init cursors (coalesced)
__global__ void k_scanC() {
    int i = blockIdx.x * 256 + threadIdx.x;
    if (i < N_NODES) {
        int o = d_off[i] + d_blkoff[i >> 10];
        d_off[i] = o;
        d_cur[i] = o;
    }
}

// ---------------- place edges into dst-sorted source list --------------------
__global__ void k_place(const void* __restrict__ ei) {
    unsigned int e = blockIdx.x * blockDim.x + threadIdx.x;
    if (e >= N_EDGES) return;
    int r = load_edge(ei, e);
    int c = load_edge(ei, N_EDGES + e);
    if ((unsigned)r >= N_NODES || (unsigned)c >= N_NODES) return;
    int pos = atomicAdd(&d_cur[c], 1);
    d_src[pos] = r;
}

// ---------------- layer-1 aggregate + relu (no block barrier) ----------------
// 16 lanes per node, 2 nodes per warp; writes x1 as fp16.
__global__ __launch_bounds__(256) void k_agg1(const float* __restrict__ b1) {
    int g = blockIdx.x * 256 + threadIdx.x;
    int lane = g & 15;
    int n = g >> 4;
    if (n >= N_NODES) return;

    const __half* g1 = d_g1;
    size_t ch = (size_t)lane * 4;
    float4 s0 = h4_to_f4(*(const uint2*)&g1[(size_t)n * HIDDEN + ch]);  // self
    float4 s1 = make_float4(0.f, 0.f, 0.f, 0.f);
    float4 s2 = make_float4(0.f, 0.f, 0.f, 0.f);
    float4 s3 = make_float4(0.f, 0.f, 0.f, 0.f);
    int beg = d_off[n], end = d_off[n + 1];
    int i = beg;
    for (; i + 3 < end; i += 4) {
        int a0 = d_src[i],     a1 = d_src[i + 1];
        int a2 = d_src[i + 2], a3 = d_src[i + 3];
        uint2 r0 = *(const uint2*)&g1[(size_t)a0 * HIDDEN + ch];
        uint2 r1 = *(const uint2*)&g1[(size_t)a1 * HIDDEN + ch];
        uint2 r2 = *(const uint2*)&g1[(size_t)a2 * HIDDEN + ch];
        uint2 r3 = *(const uint2*)&g1[(size_t)a3 * HIDDEN + ch];
        float4 v0 = h4_to_f4(r0), v1 = h4_to_f4(r1);
        float4 v2 = h4_to_f4(r2), v3 = h4_to_f4(r3);
        s0.x += v0.x; s0.y += v0.y; s0.z += v0.z; s0.w += v0.w;
        s1.x += v1.x; s1.y += v1.y; s1.z += v1.z; s1.w += v1.w;
        s2.x += v2.x; s2.y += v2.y; s2.z += v2.z; s2.w += v2.w;
        s3.x += v3.x; s3.y += v3.y; s3.z += v3.z; s3.w += v3.w;
    }
    for (; i < end; i++) {
        float4 v = h4_to_f4(*(const uint2*)&g1[(size_t)d_src[i] * HIDDEN + ch]);
        s0.x += v.x; s0.y += v.y; s0.z += v.z; s0.w += v.w;
    }
    s0.x += s1.x + s2.x + s3.x;
    s0.y += s1.y + s2.y + s3.y;
    s0.z += s1.z + s2.z + s3.z;
    s0.w += s1.w + s2.w + s3.w;
    float di = d_dinv[n];
    float4 bb = *(const float4*)&b1[lane * 4];
    __half2 h0 = __floats2half2_rn(fmaxf(di * s0.x + bb.x, 0.f),
                                   fmaxf(di * s0.y + bb.y, 0.f));
    __half2 h1 = __floats2half2_rn(fmaxf(di * s0.z + bb.z, 0.f),
                                   fmaxf(di * s0.w + bb.w, 0.f));
    uint2 o;
    o.x = *reinterpret_cast<uint32_t*>(&h0);
    o.y = *reinterpret_cast<uint32_t*>(&h1);
    *(uint2*)&d_x1[(size_t)n * HIDDEN + ch] = o;
}

// ---------------- g2 = dinv*(x1 @ W2), dense, 1 thread/node, fp16 out --------
#define W2T_STRIDE 65
__global__ __launch_bounds__(256) void k_mid(const float* __restrict__ W2) {
    __shared__ float w2t[LOC_OUT * W2T_STRIDE];  // w2t[j*65+k] = W2[k*16+j]
    int tid = threadIdx.x;
    for (int i = tid; i < HIDDEN * LOC_OUT; i += 256) {
        int k = i >> 4, j = i & 15;
        w2t[j * W2T_STRIDE + k] = W2[i];
    }
    __syncthreads();

    int n = blockIdx.x * 256 + tid;
    if (n >= N_NODES) return;

    float acc[LOC_OUT];
    #pragma unroll
    for (int j = 0; j < LOC_OUT; j++) acc[j] = 0.f;

    const uint4* xr = (const uint4*)&d_x1[(size_t)n * HIDDEN];
    #pragma unroll
    for (int u = 0; u < 8; u++) {                // 8 x uint4 = 64 halves
        uint4 r = xr[u];
        float f[8];
        {
            float2 p;
            p = __half22float2(*reinterpret_cast<__half2*>(&r.x)); f[0]=p.x; f[1]=p.y;
            p = __half22float2(*reinterpret_cast<__half2*>(&r.y)); f[2]=p.x; f[3]=p.y;
            p = __half22float2(*reinterpret_cast<__half2*>(&r.z)); f[4]=p.x; f[5]=p.y;
            p = __half22float2(*reinterpret_cast<__half2*>(&r.w)); f[6]=p.x; f[7]=p.y;
        }
        #pragma unroll
        for (int kk = 0; kk < 8; kk++) {
            float x = f[kk];
            int kb = u * 8 + kk;
            #pragma unroll
            for (int j = 0; j < LOC_OUT; j++)
                acc[j] += x * w2t[j * W2T_STRIDE + kb];
        }
    }

    float di = d_dinv[n];
    uint4 o0, o1;
    __half2 h;
    h = __floats2half2_rn(di*acc[0],  di*acc[1]);  o0.x = *reinterpret_cast<uint32_t*>(&h);
    h = __floats2half2_rn(di*acc[2],  di*acc[3]);  o0.y = *reinterpret_cast<uint32_t*>(&h);
    h = __floats2half2_rn(di*acc[4],  di*acc[5]);  o0.z = *reinterpret_cast<uint32_t*>(&h);
    h = __floats2half2_rn(di*acc[6],  di*acc[7]);  o0.w = *reinterpret_cast<uint32_t*>(&h);
    h = __floats2half2_rn(di*acc[8],  di*acc[9]);  o1.x = *reinterpret_cast<uint32_t*>(&h);
    h = __floats2half2_rn(di*acc[10], di*acc[11]); o1.y = *reinterpret_cast<uint32_t*>(&h);
    h = __floats2half2_rn(di*acc[12], di*acc[13]); o1.z = *reinterpret_cast<uint32_t*>(&h);
    h = __floats2half2_rn(di*acc[14], di*acc[15]); o1.w = *reinterpret_cast<uint32_t*>(&h);
    uint4* dst = (uint4*)&d_g2h[(size_t)n * LOC_OUT];
    dst[0] = o0;
    dst[1] = o1;
}

// ---------------- layer-2 aggregate (fp16 gather):  x2 = dinv*sum + b2 -------
__global__ __launch_bounds__(256) void k_agg2(const float* __restrict__ b2) {
    int tid = threadIdx.x;
    int lane = tid & 3;
    int n = blockIdx.x * 64 + (tid >> 2);
    if (n >= N_NODES) return;

    const __half* g2 = d_g2h;
    size_t ch = (size_t)lane * 4;
    float4 s0 = h4_to_f4(*(const uint2*)&g2[(size_t)n * LOC_OUT + ch]);  // self
    float4 s1 = make_float4(0.f, 0.f, 0.f, 0.f);
    float4 s2 = make_float4(0.f, 0.f, 0.f, 0.f);
    float4 s3 = make_float4(0.f, 0.f, 0.f, 0.f);
    int beg = d_off[n], end = d_off[n + 1];
    int i = beg;
    for (; i + 3 < end; i += 4) {
        int a0 = d_src[i],     a1 = d_src[i + 1];
        int a2 = d_src[i + 2], a3 = d_src[i + 3];
        float4 v0 = h4_to_f4(*(const uint2*)&g2[(size_t)a0 * LOC_OUT + ch]);
        float4 v1 = h4_to_f4(*(const uint2*)&g2[(size_t)a1 * LOC_OUT + ch]);
        float4 v2 = h4_to_f4(*(const uint2*)&g2[(size_t)a2 * LOC_OUT + ch]);
        float4 v3 = h4_to_f4(*(const uint2*)&g2[(size_t)a3 * LOC_OUT + ch]);
        s0.x += v0.x; s0.y += v0.y; s0.z += v0.z; s0.w += v0.w;
        s1.x += v1.x; s1.y += v1.y; s1.z += v1.z; s1.w += v1.w;
        s2.x += v2.x; s2.y += v2.y; s2.z += v2.z; s2.w += v2.w;
        s3.x += v3.x; s3.y += v3.y; s3.z += v3.z; s3.w += v3.w;
    }
    for (; i < end; i++) {
        float4 v = h4_to_f4(*(const uint2*)&g2[(size_t)d_src[i] * LOC_OUT + ch]);
        s0.x += v.x; s0.y += v.y; s0.z += v.z; s0.w += v.w;
    }
    s0.x += s1.x + s2.x + s3.x;
    s0.y += s1.y + s2.y + s3.y;
    s0.z += s1.z + s2.z + s3.z;
    s0.w += s1.w + s2.w + s3.w;
    float di = d_dinv[n];
    float4 bb = *(const float4*)&b2[lane * 4];
    float4 r;
    r.x = di * s0.x + bb.x;
    r.y = di * s0.y + bb.y;
    r.z = di * s0.z + bb.z;
    r.w = di * s0.w + bb.w;
    ((float4*)d_x2)[n * 4 + lane] = r;
}

// ---------------- final: attention pool over {x2, glob} + linear head --------
__global__ __launch_bounds__(256) void k_final(const float* __restrict__ glob,
                                               const float* __restrict__ aw1,
                                               const float* __restrict__ ab1,
                                               const float* __restrict__ aw2,
                                               const float* __restrict__ lw,
                                               const float* __restrict__ lb,
                                               float* __restrict__ out) {
    __shared__ float s_aw1[256], s_ab1[16], s_aw2[16];
    __shared__ float s_lw[LOC_OUT * OUT_CH], s_lb[OUT_CH];
    int tid = threadIdx.x;
    if (tid < 256) s_aw1[tid] = aw1[tid];
    if (tid < 16) { s_ab1[tid] = ab1[tid]; s_aw2[tid] = aw2[tid]; }
    for (int i = tid; i < LOC_OUT * OUT_CH; i += 256) s_lw[i] = lw[i];
    if (tid < OUT_CH) s_lb[tid] = lb[tid];
    __syncthreads();

    int n = blockIdx.x * 256 + tid;
    if (n >= N_NODES) return;
    float z0[16], z1[16];
    const float4* x2 = (const float4*)&d_x2[n * LOC_OUT];
    const float4* gl = (const float4*)&glob[n * LOC_OUT];
    #pragma unroll
    for (int q = 0; q < 4; q++) {
        float4 a = x2[q], e = gl[q];
        z0[q*4+0] = a.x; z0[q*4+1] = a.y; z0[q*4+2] = a.z; z0[q*4+3] = a.w;
        z1[q*4+0] = e.x; z1[q*4+1] = e.y; z1[q*4+2] = e.z; z1[q*4+3] = e.w;
    }
    float w0 = 0.f, w1 = 0.f;
    #pragma unroll
    for (int j = 0; j < 16; j++) {
        float s0 = s_ab1[j], s1 = s_ab1[j];
        #pragma unroll
        for (int i2 = 0; i2 < 16; i2++) {
            s0 += z0[i2] * s_aw1[i2 * 16 + j];
            s1 += z1[i2] * s_aw1[i2 * 16 + j];
        }
        w0 += tanhf(s0) * s_aw2[j];
        w1 += tanhf(s1) * s_aw2[j];
    }
    float beta0 = 1.f / (1.f + expf(w1 - w0));   // softmax over 2 slots
    float beta1 = 1.f - beta0;
    float emb[16];
    #pragma unroll
    for (int i2 = 0; i2 < 16; i2++) emb[i2] = beta0 * z0[i2] + beta1 * z1[i2];
    #pragma unroll
    for (int j = 0; j < OUT_CH; j++) {
        float o = s_lb[j];
        #pragma unroll
        for (int i2 = 0; i2 < 16; i2++) o += emb[i2] * s_lw[i2 * OUT_CH + j];
        out[(size_t)n * OUT_CH + j] = o;
    }
}

// ---------------- launch: fork gemm1 || (scan -> place), join at agg1 --------
extern "C" void kernel_launch(void* const* d_in, const int* in_sizes, int n_in,
                              void* d_out, int out_size) {
    const float* X    = (const float*)d_in[0];
    const void*  ei   = d_in[1];
    const float* glob = (const float*)d_in[2];
    const float* W1   = (const float*)d_in[3];
    const float* b1   = (const float*)d_in[4];
    const float* W2   = (const float*)d_in[5];
    const float* b2   = (const float*)d_in[6];
    const float* aw1  = (const float*)d_in[7];
    const float* ab1  = (const float*)d_in[8];
    const float* aw2  = (const float*)d_in[9];
    const float* lw   = (const float*)d_in[10];
    const float* lb   = (const float*)d_in[11];
    float* out = (float*)d_out;

    // Side stream + events. Host code runs only on the correctness call and
    // the capture call (graph replays re-execute captured GPU work only), so
    // per-call creation is cheap; not destroyed to avoid teardown inside an
    // active capture sequence.
    cudaStream_t s2;
    cudaEvent_t evFork, evJoin;
    cudaStreamCreateWithFlags(&s2, cudaStreamNonBlocking);
    cudaEventCreateWithFlags(&evFork, cudaEventDisableTiming);
    cudaEventCreateWithFlags(&evJoin, cudaEventDisableTiming);

    k_init  <<<(N_NODES + 255) / 256, 256>>>();                 // 0
    k_detect<<<1, 256>>>((const int*)ei);                       // 1
    k_count <<<(N_EDGES + 255) / 256, 256>>>(ei);               // 2

    cudaEventRecord(evFork, 0);
    cudaStreamWaitEvent(s2, evFork, 0);
    k_gemm1 <<<(N_NODES + 127) / 128, 256, 0, s2>>>(X, W1);     // 3 <- profiled
    cudaEventRecord(evJoin, s2);

    k_scanA <<<NSCB, 1024>>>();                                 // 4
    k_scanB <<<1, 128>>>();                                     // 5
    k_scanC <<<(N_NODES + 255) / 256, 256>>>();                 // 6
    k_place <<<(N_EDGES + 255) / 256, 256>>>(ei);               // 7

    cudaStreamWaitEvent(0, evJoin, 0);                          // join
    k_agg1  <<<(N_NODES * 16 + 255) / 256, 256>>>(b1);          // 8
    k_mid   <<<(N_NODES + 255) / 256, 256>>>(W2);               // 9
    k_agg2  <<<(N_NODES + 63) / 64, 256>>>(b2);                 // 10
    k_final <<<(N_NODES + 255) / 256, 256>>>(glob, aw1, ab1, aw2, lw, lb, out);  // 11
}